// round 6
// baseline (speedup 1.0000x reference)
#include <cuda_runtime.h>
#include <math.h>

// Problem constants
#define BB 2
#define NQ 300
#define CC 256
#define HH 8
#define DD 32
#define LTOT 5376
#define L1SZ 4096   // 64x64
#define L2OFF 4096
#define L2SZ 1024   // 32x32
#define L3OFF 5120
#define L3SZ 256    // 16x16
#define NL (NQ*LTOT)            // 1,612,800
#define NTILES_L 42             // 5376 / 128
#define NROWS (BB*HH*NQ)        // 4800
#define SCALE 0.17677669529663687f  // 1/sqrt(32)

// ---------------- scratch (device globals; allocation-free) ----------------
__device__ float g_q[BB*NQ*CC];
__device__ float g_k[BB*LTOT*CC];
__device__ float g_v[BB*LTOT*CC];
__device__ float g_attn[(size_t)BB*HH*NQ*LTOT];   // raw scaled logits (never overwritten)
__device__ float g_f2[BB*NQ*L2SZ*HH];
__device__ float g_f3[BB*NQ*L3SZ*HH];
__device__ float g_x[BB*NQ*CC];
__device__ float g_pm[NROWS*NTILES_L];   // per-tile row max
__device__ float g_ps[NROWS*NTILES_L];   // per-tile row sumexp
__device__ float g_rowm[NROWS];          // global row max
__device__ float g_rowinv[NROWS];        // 1/sumexp

// ---------------- projection GEMM: C[M,256] = A[M,256] @ W[256,256] (+bias) ----
// BM=64, BN=64, BK=16, 128 threads, per-thread 8x4  (proven R1 kernel)
__global__ void proj_gemm_kernel(const float* __restrict__ A, const float* __restrict__ W,
                                 const float* __restrict__ bias, float* __restrict__ Cout,
                                 int M)
{
    __shared__ float As[16][68];   // [k][m]
    __shared__ float Bs[16][68];   // [k][n]
    int tid = threadIdx.x;
    int bm = blockIdx.y * 64;
    int bn = blockIdx.x * 64;
    int tm = (tid >> 4) * 8;
    int tn = (tid & 15) * 4;
    float acc[8][4];
    #pragma unroll
    for (int i = 0; i < 8; i++)
        #pragma unroll
        for (int j = 0; j < 4; j++) acc[i][j] = 0.f;

    for (int k0 = 0; k0 < 256; k0 += 16) {
        for (int i = tid; i < 64*16; i += 128) {
            int m = i >> 4, kk = i & 15;
            int row = bm + m;
            As[kk][m] = (row < M) ? A[(size_t)row*256 + k0 + kk] : 0.f;
        }
        for (int i = tid; i < 16*64; i += 128) {
            int kk = i >> 6, n = i & 63;
            Bs[kk][n] = W[(k0 + kk)*256 + bn + n];
        }
        __syncthreads();
        #pragma unroll
        for (int kk = 0; kk < 16; kk++) {
            float a[8], bb[4];
            *(float4*)&a[0] = *(const float4*)&As[kk][tm];
            *(float4*)&a[4] = *(const float4*)&As[kk][tm+4];
            *(float4*)&bb[0] = *(const float4*)&Bs[kk][tn];
            #pragma unroll
            for (int i = 0; i < 8; i++)
                #pragma unroll
                for (int j = 0; j < 4; j++)
                    acc[i][j] = fmaf(a[i], bb[j], acc[i][j]);
        }
        __syncthreads();
    }
    #pragma unroll
    for (int i = 0; i < 8; i++) {
        int row = bm + tm + i;
        if (row >= M) continue;
        #pragma unroll
        for (int j = 0; j < 4; j++) {
            float v = acc[i][j];
            if (bias) v += bias[bn + tn + j];
            Cout[(size_t)row*256 + bn + tn + j] = v;
        }
    }
}

// ---------------- attention logits + per-tile softmax partials --------------
// per (b,h): BM=64 (n), BN=128 (l), K=32, 256 threads, per-thread 8x4
__global__ void attn_gemm_kernel(const float* __restrict__ Q, const float* __restrict__ K,
                                 float* __restrict__ attn,
                                 float* __restrict__ pm, float* __restrict__ ps)
{
    __shared__ float QsT[32][68];    // [k][m]
    __shared__ float KsT[32][132];   // [k][l]
    int tid = threadIdx.x;
    int bh = blockIdx.z;            // 0..15
    int b = bh >> 3, h = bh & 7;
    int nbase = blockIdx.y * 64;
    int lbase = blockIdx.x * 128;
    int tm = (tid >> 5) * 8;        // warp owns rows tm..tm+7
    int tn = (tid & 31) * 4;
    int lane = tid & 31;

    for (int i = tid; i < 64*32; i += 256) {
        int m = i >> 5, kk = i & 31;
        int row = nbase + m;
        QsT[kk][m] = (row < NQ) ? Q[((size_t)b*NQ + row)*CC + h*32 + kk] : 0.f;
    }
    for (int i = tid; i < 128*32; i += 256) {
        int l = i >> 5, kk = i & 31;
        KsT[kk][l] = K[((size_t)b*LTOT + lbase + l)*CC + h*32 + kk];
    }
    __syncthreads();

    float acc[8][4];
    #pragma unroll
    for (int i = 0; i < 8; i++)
        #pragma unroll
        for (int j = 0; j < 4; j++) acc[i][j] = 0.f;

    #pragma unroll
    for (int kk = 0; kk < 32; kk++) {
        float a[8], bb[4];
        *(float4*)&a[0] = *(const float4*)&QsT[kk][tm];
        *(float4*)&a[4] = *(const float4*)&QsT[kk][tm+4];
        *(float4*)&bb[0] = *(const float4*)&KsT[kk][tn];
        #pragma unroll
        for (int i = 0; i < 8; i++)
            #pragma unroll
            for (int j = 0; j < 4; j++)
                acc[i][j] = fmaf(a[i], bb[j], acc[i][j]);
    }

    #pragma unroll
    for (int i = 0; i < 8; i++) {
        int row = nbase + tm + i;
        float o0 = acc[i][0] * SCALE;
        float o1 = acc[i][1] * SCALE;
        float o2 = acc[i][2] * SCALE;
        float o3 = acc[i][3] * SCALE;
        if (row < NQ) {
            float4 o; o.x = o0; o.y = o1; o.z = o2; o.w = o3;
            *(float4*)&attn[((size_t)bh*NQ + row)*LTOT + lbase + tn] = o;
        }
        // per-row softmax partials over this 128-col tile (warp-wide reduce)
        float m = fmaxf(fmaxf(o0, o1), fmaxf(o2, o3));
        #pragma unroll
        for (int s = 16; s > 0; s >>= 1)
            m = fmaxf(m, __shfl_xor_sync(0xffffffffu, m, s));
        float sum = __expf(o0 - m) + __expf(o1 - m) + __expf(o2 - m) + __expf(o3 - m);
        #pragma unroll
        for (int s = 16; s > 0; s >>= 1)
            sum += __shfl_xor_sync(0xffffffffu, sum, s);
        if (lane == 0 && row < NQ) {
            size_t pidx = ((size_t)bh*NQ + row)*NTILES_L + blockIdx.x;
            pm[pidx] = m;
            ps[pidx] = sum;
        }
    }
}

// ---------------- combine per-tile partials into per-row (max, 1/sum) -------
__global__ void softstats_kernel(const float* __restrict__ pm, const float* __restrict__ ps,
                                 float* __restrict__ rowm, float* __restrict__ rowinv)
{
    int row = blockIdx.x * 8 + (threadIdx.x >> 5);
    int lane = threadIdx.x & 31;
    size_t base = (size_t)row * NTILES_L;
    float m1 = (lane < NTILES_L) ? pm[base + lane] : -1e30f;
    float m2 = (lane + 32 < NTILES_L) ? pm[base + lane + 32] : -1e30f;
    float m = fmaxf(m1, m2);
    #pragma unroll
    for (int s = 16; s > 0; s >>= 1)
        m = fmaxf(m, __shfl_xor_sync(0xffffffffu, m, s));
    float s1 = (lane < NTILES_L) ? ps[base + lane] * __expf(m1 - m) : 0.f;
    float s2 = (lane + 32 < NTILES_L) ? ps[base + lane + 32] * __expf(m2 - m) : 0.f;
    float ssum = s1 + s2;
    #pragma unroll
    for (int s = 16; s > 0; s >>= 1)
        ssum += __shfl_xor_sync(0xffffffffu, ssum, s);
    if (lane == 0) {
        rowm[row] = m;
        rowinv[row] = 1.f / ssum;
    }
}

// ---------------- f2/f3 small fields: relu(ap @ W + b), channel-last --------
__global__ void f23_kernel(const float* __restrict__ attn,
                           const float* __restrict__ W2, const float* __restrict__ b2,
                           const float* __restrict__ W3, const float* __restrict__ b3,
                           float* __restrict__ f2o, float* __restrict__ f3o)
{
    int bn = blockIdx.y;
    int b = bn / NQ, n = bn % NQ;
    int j = blockIdx.x * blockDim.x + threadIdx.x;
    if (j >= L2SZ + L3SZ) return;

    int lidx = (j < L2SZ) ? (L2OFF + j) : (L3OFF + (j - L2SZ));
    size_t base = ((size_t)(b*HH)*NQ + n)*LTOT + lidx;
    float a[8];
    #pragma unroll
    for (int hh = 0; hh < 8; hh++)
        a[hh] = attn[base + (size_t)hh * NL];

    if (j < L2SZ) {
        float* dst = f2o + ((size_t)bn * L2SZ + j) * 8;
        #pragma unroll
        for (int h = 0; h < 8; h++) {
            float s = b2[h];
            #pragma unroll
            for (int hh = 0; hh < 8; hh++) s = fmaf(a[hh], W2[hh*8 + h], s);
            dst[h] = fmaxf(s, 0.f);
        }
    } else {
        int jj = j - L2SZ;
        float* dst = f3o + ((size_t)bn * L3SZ + jj) * 8;
        #pragma unroll
        for (int h = 0; h < 8; h++) {
            float s = b3[h];
            #pragma unroll
            for (int hh = 0; hh < 8; hh++) s = fmaf(a[hh], W3[hh*8 + h], s);
            dst[h] = fmaxf(s, 0.f);
        }
    }
}

// ---------------- fused mask: f1 + bilinear(f2) + bilinear(f3), dot Wm, relu -
__global__ void mask_kernel(const float* __restrict__ attn,
                            const float* __restrict__ f2f, const float* __restrict__ f3f,
                            const float* __restrict__ W1, const float* __restrict__ b1,
                            const float* __restrict__ Wm, const float* __restrict__ bm,
                            float* __restrict__ outmask)
{
    __shared__ float sW1[64], sb1[8], sWm[24], sbm[1];
    int t = threadIdx.x;
    if (t < 64) sW1[t] = W1[t];
    if (t < 8)  sb1[t] = b1[t];
    if (t < 24) sWm[t] = Wm[t];
    if (t == 0) sbm[0] = bm[0];
    __syncthreads();

    int bn = blockIdx.y;
    int b = bn / NQ, n = bn % NQ;
    int p = blockIdx.x * blockDim.x + t;
    int Y = p >> 6, X = p & 63;

    size_t base = ((size_t)(b*HH)*NQ + n)*LTOT + p;
    float a[8];
    #pragma unroll
    for (int hh = 0; hh < 8; hh++)
        a[hh] = attn[base + (size_t)hh * NL];

    float acc = sbm[0];
    #pragma unroll
    for (int h = 0; h < 8; h++) {
        float s = sb1[h];
        #pragma unroll
        for (int hh = 0; hh < 8; hh++) s = fmaf(a[hh], sW1[hh*8 + h], s);
        acc = fmaf(fmaxf(s, 0.f), sWm[h], acc);
    }

    {   // f2: bilinear from 32x32
        float ry = fminf(fmaxf(0.5f*(float)Y - 0.25f, 0.f), 31.f);
        float rx = fminf(fmaxf(0.5f*(float)X - 0.25f, 0.f), 31.f);
        int y0 = (int)ry, x0 = (int)rx;
        int y1 = min(y0+1, 31), x1 = min(x0+1, 31);
        float wy = ry - (float)y0, wx = rx - (float)x0;
        float w00 = (1.f-wy)*(1.f-wx), w01 = (1.f-wy)*wx, w10 = wy*(1.f-wx), w11 = wy*wx;
        const float* fb = f2f + (size_t)bn * (L2SZ*8);
        const float* t00 = fb + (y0*32 + x0)*8;
        const float* t01 = fb + (y0*32 + x1)*8;
        const float* t10 = fb + (y1*32 + x0)*8;
        const float* t11 = fb + (y1*32 + x1)*8;
        #pragma unroll
        for (int h = 0; h < 8; h++) {
            float v = w00*t00[h] + w01*t01[h] + w10*t10[h] + w11*t11[h];
            acc = fmaf(v, sWm[8 + h], acc);
        }
    }
    {   // f3: bilinear from 16x16
        float ry = fminf(fmaxf(0.25f*(float)Y - 0.375f, 0.f), 15.f);
        float rx = fminf(fmaxf(0.25f*(float)X - 0.375f, 0.f), 15.f);
        int y0 = (int)ry, x0 = (int)rx;
        int y1 = min(y0+1, 15), x1 = min(x0+1, 15);
        float wy = ry - (float)y0, wx = rx - (float)x0;
        float w00 = (1.f-wy)*(1.f-wx), w01 = (1.f-wy)*wx, w10 = wy*(1.f-wx), w11 = wy*wx;
        const float* fb = f3f + (size_t)bn * (L3SZ*8);
        const float* t00 = fb + (y0*16 + x0)*8;
        const float* t01 = fb + (y0*16 + x1)*8;
        const float* t10 = fb + (y1*16 + x0)*8;
        const float* t11 = fb + (y1*16 + x1)*8;
        #pragma unroll
        for (int h = 0; h < 8; h++) {
            float v = w00*t00[h] + w01*t01[h] + w10*t10[h] + w11*t11[h];
            acc = fmaf(v, sWm[16 + h], acc);
        }
    }
    outmask[(size_t)bn * L1SZ + p] = fmaxf(acc, 0.f);
}

// ---------------- zero ----
__global__ void zero_kernel(float* __restrict__ p, int n)
{
    int i = blockIdx.x * blockDim.x + threadIdx.x;
    if (i < n) p[i] = 0.f;
}

// ---------------- AV: probs computed on the fly from raw logits -------------
// per (b,h): BM=64 (n), BN=32 (d), BK=32, 128 threads, L split x8 with atomics
__global__ void av_kernel(const float* __restrict__ attn, const float* __restrict__ V,
                          const float* __restrict__ rowm, const float* __restrict__ rowinv,
                          float* __restrict__ X)
{
    __shared__ float As[32][68];   // [k][m] holds probabilities
    __shared__ float Bs[32][32];   // [k][d]
    __shared__ float srm[64], sri[64];
    int tid = threadIdx.x;
    int bh = blockIdx.z;
    int b = bh >> 3, h = bh & 7;
    int nbase = blockIdx.y * 64;
    int l0 = blockIdx.x * 672;     // 8-way L split: 5376/8 = 672
    int tm = (tid >> 4) * 8;
    int tn = (tid & 15) * 2;

    if (tid < 64) {
        int row = nbase + tid;
        bool ok = row < NQ;
        srm[tid] = ok ? rowm[(size_t)bh*NQ + row] : 0.f;
        sri[tid] = ok ? rowinv[(size_t)bh*NQ + row] : 0.f;
    }
    __syncthreads();

    float acc[8][2];
    #pragma unroll
    for (int i = 0; i < 8; i++) { acc[i][0] = 0.f; acc[i][1] = 0.f; }

    for (int k0 = l0; k0 < l0 + 672; k0 += 32) {
        for (int i = tid; i < 64*32; i += 128) {
            int m = i >> 5, kk = i & 31;
            int row = nbase + m;
            float p = 0.f;
            if (row < NQ) {
                float v = attn[((size_t)bh*NQ + row)*LTOT + k0 + kk];
                p = __expf(v - srm[m]) * sri[m];
            }
            As[kk][m] = p;
        }
        for (int i = tid; i < 32*32; i += 128) {
            int kk = i >> 5, d = i & 31;
            Bs[kk][d] = V[((size_t)b*LTOT + k0 + kk)*CC + h*32 + d];
        }
        __syncthreads();
        #pragma unroll
        for (int kk = 0; kk < 32; kk++) {
            float a[8];
            *(float4*)&a[0] = *(const float4*)&As[kk][tm];
            *(float4*)&a[4] = *(const float4*)&As[kk][tm+4];
            float b0 = Bs[kk][tn], b1 = Bs[kk][tn+1];
            #pragma unroll
            for (int i = 0; i < 8; i++) {
                acc[i][0] = fmaf(a[i], b0, acc[i][0]);
                acc[i][1] = fmaf(a[i], b1, acc[i][1]);
            }
        }
        __syncthreads();
    }
    #pragma unroll
    for (int i = 0; i < 8; i++) {
        int row = nbase + tm + i;
        if (row >= NQ) continue;
        atomicAdd(&X[((size_t)b*NQ + row)*CC + h*32 + tn    ], acc[i][0]);
        atomicAdd(&X[((size_t)b*NQ + row)*CC + h*32 + tn + 1], acc[i][1]);
    }
}

// ---------------- launch ----
extern "C" void kernel_launch(void* const* d_in, const int* in_sizes, int n_in,
                              void* d_out, int out_size)
{
    const float* query = (const float*)d_in[0];
    const float* key   = (const float*)d_in[1];
    const float* value = (const float*)d_in[2];
    const float* Wq = (const float*)d_in[5];
    const float* Wk = (const float*)d_in[6];
    const float* Wv = (const float*)d_in[7];
    const float* Wp = (const float*)d_in[8];
    const float* bp = (const float*)d_in[9];
    const float* W1 = (const float*)d_in[10];
    const float* b1 = (const float*)d_in[11];
    const float* W2 = (const float*)d_in[12];
    const float* b2 = (const float*)d_in[13];
    const float* W3 = (const float*)d_in[14];
    const float* b3 = (const float*)d_in[15];
    const float* Wm = (const float*)d_in[16];
    const float* bm = (const float*)d_in[17];

    float* out_x    = (float*)d_out;
    float* out_mask = (float*)d_out + BB*NQ*CC;

    float *gq, *gk, *gv, *gattn, *gf2, *gf3, *gx, *gpm, *gps, *grm, *gri;
    cudaGetSymbolAddress((void**)&gq,    g_q);
    cudaGetSymbolAddress((void**)&gk,    g_k);
    cudaGetSymbolAddress((void**)&gv,    g_v);
    cudaGetSymbolAddress((void**)&gattn, g_attn);
    cudaGetSymbolAddress((void**)&gf2,   g_f2);
    cudaGetSymbolAddress((void**)&gf3,   g_f3);
    cudaGetSymbolAddress((void**)&gx,    g_x);
    cudaGetSymbolAddress((void**)&gpm,   g_pm);
    cudaGetSymbolAddress((void**)&gps,   g_ps);
    cudaGetSymbolAddress((void**)&grm,   g_rowm);
    cudaGetSymbolAddress((void**)&gri,   g_rowinv);

    // 1) projections (all via the proven 64x64 high-occupancy kernel)
    proj_gemm_kernel<<<dim3(4, 10),  128>>>(query, Wq, nullptr, gq, BB*NQ);
    proj_gemm_kernel<<<dim3(4, 168), 128>>>(key,   Wk, nullptr, gk, BB*LTOT);
    proj_gemm_kernel<<<dim3(4, 168), 128>>>(value, Wv, nullptr, gv, BB*LTOT);

    // 2) attention logits + per-tile softmax partials
    attn_gemm_kernel<<<dim3(NTILES_L, 5, 16), 256>>>(gq, gk, gattn, gpm, gps);

    // 3) per-row softmax stats (replaces the full softmax pass)
    softstats_kernel<<<NROWS/8, 256>>>(gpm, gps, grm, gri);

    // 4) mask path (reads raw logits)
    f23_kernel<<<dim3(5, 600), 256>>>(gattn, W2, b2, W3, b3, gf2, gf3);
    mask_kernel<<<dim3(32, 600), 128>>>(gattn, gf2, gf3, W1, b1, Wm, bm, out_mask);

    // 5) AV with on-the-fly normalization, 8-way L split
    zero_kernel<<<(BB*NQ*CC + 255)/256, 256>>>(gx, BB*NQ*CC);
    av_kernel<<<dim3(8, 5, 16), 128>>>(gattn, gv, grm, gri, gx);

    // 6) output projection
    proj_gemm_kernel<<<dim3(4, 10), 128>>>(gx, Wp, bp, out_x, BB*NQ);
}

// round 10
// speedup vs baseline: 1.4263x; 1.4263x over previous
#include <cuda_runtime.h>
#include <cuda_bf16.h>
#include <cstdint>
#include <math.h>

// Problem constants
#define BB 2
#define NQ 300
#define CC 256
#define HH 8
#define DD 32
#define LTOT 5376
#define L1SZ 4096   // 64x64
#define L2OFF 4096
#define L2SZ 1024   // 32x32
#define L3OFF 5120
#define L3SZ 256    // 16x16
#define NL (NQ*LTOT)            // 1,612,800
#define NTILES_L 42             // 5376 / 128
#define NROWS (BB*HH*NQ)        // 4800
#define MKV (BB*LTOT)           // 10752 rows for K/V projections
#define SCALE 0.17677669529663687f  // 1/sqrt(32)

// ---------------- scratch (device globals; allocation-free) ----------------
__device__ float g_q[BB*NQ*CC];
__device__ float g_k[BB*LTOT*CC];
__device__ float g_v[BB*LTOT*CC];
__device__ float g_attn[(size_t)BB*HH*NQ*LTOT];   // raw scaled logits
__device__ float g_f2[BB*NQ*L2SZ*HH];
__device__ float g_f3[BB*NQ*L3SZ*HH];
__device__ float g_x[BB*NQ*CC];
__device__ float g_pm[NROWS*NTILES_L];
__device__ float g_ps[NROWS*NTILES_L];
__device__ float g_rowm[NROWS];
__device__ float g_rowinv[NROWS];
__device__ __nv_bfloat16 g_kimg[(size_t)MKV*512];   // key   hi|lo split image [r][512]
__device__ __nv_bfloat16 g_vimg[(size_t)MKV*512];   // value hi|lo split image
__device__ __nv_bfloat16 g_wk[256*512];             // Wk^T  hi|lo image [n][512]
__device__ __nv_bfloat16 g_wv[256*512];             // Wv^T  hi|lo image

// ================= mma.sync helpers =================
__device__ __forceinline__ uint32_t smem_u32(const void* p) {
    uint32_t a;
    asm("{ .reg .u64 t; cvta.to.shared.u64 t, %1; cvt.u32.u64 %0, t; }" : "=r"(a) : "l"(p));
    return a;
}
#define LDSM4(r, addr) \
    asm volatile("ldmatrix.sync.aligned.m8n8.x4.shared.b16 {%0,%1,%2,%3}, [%4];" \
        : "=r"((r)[0]), "=r"((r)[1]), "=r"((r)[2]), "=r"((r)[3]) : "r"(addr))
#define MMA16816(dd, aa, b0, b1) \
    asm volatile("mma.sync.aligned.m16n8k16.row.col.f32.bf16.bf16.f32 " \
        "{%0,%1,%2,%3},{%4,%5,%6,%7},{%8,%9},{%0,%1,%2,%3};" \
        : "+f"((dd)[0]), "+f"((dd)[1]), "+f"((dd)[2]), "+f"((dd)[3]) \
        : "r"((aa)[0]), "r"((aa)[1]), "r"((aa)[2]), "r"((aa)[3]), "r"(b0), "r"(b1))

// ---------------- prep: split fp32 rows into [hi(256)|lo(256)] bf16 image ----
// thread handles 4 consecutive cols of one row
__global__ void prep_split_kernel(const float* __restrict__ A, __nv_bfloat16* __restrict__ img,
                                  int M)
{
    int idx = blockIdx.x * blockDim.x + threadIdx.x;
    if (idx >= M * 64) return;
    int r = idx >> 6, c4 = (idx & 63) * 4;
    float4 v = *(const float4*)(A + (size_t)r * 256 + c4);
    __nv_bfloat16 hi[4], lo[4];
    hi[0] = __float2bfloat16(v.x); lo[0] = __float2bfloat16(v.x - __bfloat162float(hi[0]));
    hi[1] = __float2bfloat16(v.y); lo[1] = __float2bfloat16(v.y - __bfloat162float(hi[1]));
    hi[2] = __float2bfloat16(v.z); lo[2] = __float2bfloat16(v.z - __bfloat162float(hi[2]));
    hi[3] = __float2bfloat16(v.w); lo[3] = __float2bfloat16(v.w - __bfloat162float(hi[3]));
    *(uint2*)(img + (size_t)r * 512 + c4)       = *(uint2*)hi;
    *(uint2*)(img + (size_t)r * 512 + 256 + c4) = *(uint2*)lo;
}

// ---------------- prep: W[k][n] -> Wt image [n][ hi k(256) | lo k(256) ] ----
__global__ void prep_wt_kernel(const float* __restrict__ W, __nv_bfloat16* __restrict__ img)
{
    int n = blockIdx.x;     // 0..255
    int k = threadIdx.x;    // 0..255
    float x = W[(size_t)k * 256 + n];
    __nv_bfloat16 h = __float2bfloat16(x);
    img[(size_t)n * 512 + k]       = h;
    img[(size_t)n * 512 + 256 + k] = __float2bfloat16(x - __bfloat162float(h));
}

// ---------------- tensor-core projection: C[MKV,256] = A @ W via bf16 split ----
// grid (2 n-tiles, 84 m-tiles), 256 threads (8 warps of 32x64), smem 54KB
#define PSTR 72   // smem row stride in bf16 (144B: conflict-free ldmatrix)
__global__ void __launch_bounds__(256)
proj_mma_kernel(const __nv_bfloat16* __restrict__ Aimg, const __nv_bfloat16* __restrict__ Wimg,
                float* __restrict__ Cout)
{
    extern __shared__ __align__(16) char dsm[];
    __nv_bfloat16* sA  = (__nv_bfloat16*)dsm;                    // [128][72]
    __nv_bfloat16* sB1 = (__nv_bfloat16*)(dsm + 128*PSTR*2);
    __nv_bfloat16* sB2 = (__nv_bfloat16*)(dsm + 2*128*PSTR*2);
    const int tid = threadIdx.x;
    const int lane = tid & 31, wid = tid >> 5;
    const int wm = (wid & 3) * 32;     // warp m offset within 128 tile
    const int wn = (wid >> 2) * 64;    // warp n offset within 128 tile
    const int m0 = blockIdx.y * 128;
    const int n0 = blockIdx.x * 128;

    float d[2][8][4];
    #pragma unroll
    for (int i = 0; i < 2; i++)
        #pragma unroll
        for (int j = 0; j < 8; j++)
            #pragma unroll
            for (int q = 0; q < 4; q++) d[i][j][q] = 0.f;

    const uint32_t sa_u = smem_u32(sA), sb1_u = smem_u32(sB1), sb2_u = smem_u32(sB2);

    for (int kc = 0; kc < 512; kc += 64) {
        int kc2 = (kc + 256) & 511;
        for (int i = tid; i < 1024; i += 256) {
            int r = i >> 3, c = i & 7;
            *(uint4*)(sA + r * PSTR + c * 8) =
                *(const uint4*)(Aimg + (size_t)(m0 + r) * 512 + kc + c * 8);
        }
        for (int i = tid; i < 1024; i += 256) {
            int r = i >> 3, c = i & 7;
            const __nv_bfloat16* wrow = Wimg + (size_t)(n0 + r) * 512;
            *(uint4*)(sB1 + r * PSTR + c * 8) = *(const uint4*)(wrow + kc  + c * 8);
            *(uint4*)(sB2 + r * PSTR + c * 8) = *(const uint4*)(wrow + kc2 + c * 8);
        }
        __syncthreads();
        #pragma unroll
        for (int ks = 0; ks < 4; ks++) {
            uint32_t a[2][4];
            #pragma unroll
            for (int am = 0; am < 2; am++) {
                uint32_t addr = sa_u +
                    ((uint32_t)((wm + am*16 + (lane & 15)) * PSTR + ks*16 + (lane >> 4)*8) << 1);
                LDSM4(a[am], addr);
            }
            #pragma unroll
            for (int p = 0; p < 4; p++) {
                uint32_t boff = ((uint32_t)((wn + p*16 + (lane & 7) + ((lane >> 4) << 3)) * PSTR
                                 + ks*16 + ((lane >> 3) & 1) * 8) << 1);
                uint32_t b[4];
                LDSM4(b, sb1_u + boff);
                MMA16816(d[0][2*p],   a[0], b[0], b[1]);
                MMA16816(d[0][2*p+1], a[0], b[2], b[3]);
                MMA16816(d[1][2*p],   a[1], b[0], b[1]);
                MMA16816(d[1][2*p+1], a[1], b[2], b[3]);
                LDSM4(b, sb2_u + boff);
                MMA16816(d[0][2*p],   a[0], b[0], b[1]);
                MMA16816(d[0][2*p+1], a[0], b[2], b[3]);
                MMA16816(d[1][2*p],   a[1], b[0], b[1]);
                MMA16816(d[1][2*p+1], a[1], b[2], b[3]);
            }
        }
        __syncthreads();
    }

    // epilogue: fragment -> global (row = lane/4 (+8), col pair = (lane%4)*2)
    #pragma unroll
    for (int am = 0; am < 2; am++) {
        int rbase = m0 + wm + am * 16 + (lane >> 2);
        #pragma unroll
        for (int na = 0; na < 8; na++) {
            int col = n0 + wn + na * 8 + (lane & 3) * 2;
            float* p0 = Cout + (size_t)rbase * 256 + col;
            p0[0] = d[am][na][0]; p0[1] = d[am][na][1];
            float* p1 = Cout + (size_t)(rbase + 8) * 256 + col;
            p1[0] = d[am][na][2]; p1[1] = d[am][na][3];
        }
    }
}

// ---------------- projection GEMM (small M): C[M,256] = A @ W (+bias) ----------
__global__ void proj_gemm_kernel(const float* __restrict__ A, const float* __restrict__ W,
                                 const float* __restrict__ bias, float* __restrict__ Cout,
                                 int M)
{
    __shared__ float As[16][68];
    __shared__ float Bs[16][68];
    int tid = threadIdx.x;
    int bm = blockIdx.y * 64;
    int bn = blockIdx.x * 64;
    int tm = (tid >> 4) * 8;
    int tn = (tid & 15) * 4;
    float acc[8][4];
    #pragma unroll
    for (int i = 0; i < 8; i++)
        #pragma unroll
        for (int j = 0; j < 4; j++) acc[i][j] = 0.f;

    for (int k0 = 0; k0 < 256; k0 += 16) {
        for (int i = tid; i < 64*16; i += 128) {
            int m = i >> 4, kk = i & 15;
            int row = bm + m;
            As[kk][m] = (row < M) ? A[(size_t)row*256 + k0 + kk] : 0.f;
        }
        for (int i = tid; i < 16*64; i += 128) {
            int kk = i >> 6, n = i & 63;
            Bs[kk][n] = W[(k0 + kk)*256 + bn + n];
        }
        __syncthreads();
        #pragma unroll
        for (int kk = 0; kk < 16; kk++) {
            float a[8], bb[4];
            *(float4*)&a[0] = *(const float4*)&As[kk][tm];
            *(float4*)&a[4] = *(const float4*)&As[kk][tm+4];
            *(float4*)&bb[0] = *(const float4*)&Bs[kk][tn];
            #pragma unroll
            for (int i = 0; i < 8; i++)
                #pragma unroll
                for (int j = 0; j < 4; j++)
                    acc[i][j] = fmaf(a[i], bb[j], acc[i][j]);
        }
        __syncthreads();
    }
    #pragma unroll
    for (int i = 0; i < 8; i++) {
        int row = bm + tm + i;
        if (row >= M) continue;
        #pragma unroll
        for (int j = 0; j < 4; j++) {
            float v = acc[i][j];
            if (bias) v += bias[bn + tn + j];
            Cout[(size_t)row*256 + bn + tn + j] = v;
        }
    }
}

// ---------------- attention logits + per-tile softmax partials --------------
__global__ void attn_gemm_kernel(const float* __restrict__ Q, const float* __restrict__ K,
                                 float* __restrict__ attn,
                                 float* __restrict__ pm, float* __restrict__ ps)
{
    __shared__ float QsT[32][68];
    __shared__ float KsT[32][132];
    int tid = threadIdx.x;
    int bh = blockIdx.z;
    int b = bh >> 3, h = bh & 7;
    int nbase = blockIdx.y * 64;
    int lbase = blockIdx.x * 128;
    int tm = (tid >> 5) * 8;
    int tn = (tid & 31) * 4;
    int lane = tid & 31;

    for (int i = tid; i < 64*32; i += 256) {
        int m = i >> 5, kk = i & 31;
        int row = nbase + m;
        QsT[kk][m] = (row < NQ) ? Q[((size_t)b*NQ + row)*CC + h*32 + kk] : 0.f;
    }
    for (int i = tid; i < 128*32; i += 256) {
        int l = i >> 5, kk = i & 31;
        KsT[kk][l] = K[((size_t)b*LTOT + lbase + l)*CC + h*32 + kk];
    }
    __syncthreads();

    float acc[8][4];
    #pragma unroll
    for (int i = 0; i < 8; i++)
        #pragma unroll
        for (int j = 0; j < 4; j++) acc[i][j] = 0.f;

    #pragma unroll
    for (int kk = 0; kk < 32; kk++) {
        float a[8], bb[4];
        *(float4*)&a[0] = *(const float4*)&QsT[kk][tm];
        *(float4*)&a[4] = *(const float4*)&QsT[kk][tm+4];
        *(float4*)&bb[0] = *(const float4*)&KsT[kk][tn];
        #pragma unroll
        for (int i = 0; i < 8; i++)
            #pragma unroll
            for (int j = 0; j < 4; j++)
                acc[i][j] = fmaf(a[i], bb[j], acc[i][j]);
    }

    #pragma unroll
    for (int i = 0; i < 8; i++) {
        int row = nbase + tm + i;
        float o0 = acc[i][0] * SCALE;
        float o1 = acc[i][1] * SCALE;
        float o2 = acc[i][2] * SCALE;
        float o3 = acc[i][3] * SCALE;
        if (row < NQ) {
            float4 o; o.x = o0; o.y = o1; o.z = o2; o.w = o3;
            *(float4*)&attn[((size_t)bh*NQ + row)*LTOT + lbase + tn] = o;
        }
        float m = fmaxf(fmaxf(o0, o1), fmaxf(o2, o3));
        #pragma unroll
        for (int s = 16; s > 0; s >>= 1)
            m = fmaxf(m, __shfl_xor_sync(0xffffffffu, m, s));
        float sum = __expf(o0 - m) + __expf(o1 - m) + __expf(o2 - m) + __expf(o3 - m);
        #pragma unroll
        for (int s = 16; s > 0; s >>= 1)
            sum += __shfl_xor_sync(0xffffffffu, sum, s);
        if (lane == 0 && row < NQ) {
            size_t pidx = ((size_t)bh*NQ + row)*NTILES_L + blockIdx.x;
            pm[pidx] = m;
            ps[pidx] = sum;
        }
    }
}

// ---------------- combine per-tile partials into per-row (max, 1/sum) -------
__global__ void softstats_kernel(const float* __restrict__ pm, const float* __restrict__ ps,
                                 float* __restrict__ rowm, float* __restrict__ rowinv)
{
    int row = blockIdx.x * 8 + (threadIdx.x >> 5);
    int lane = threadIdx.x & 31;
    size_t base = (size_t)row * NTILES_L;
    float m1 = (lane < NTILES_L) ? pm[base + lane] : -1e30f;
    float m2 = (lane + 32 < NTILES_L) ? pm[base + lane + 32] : -1e30f;
    float m = fmaxf(m1, m2);
    #pragma unroll
    for (int s = 16; s > 0; s >>= 1)
        m = fmaxf(m, __shfl_xor_sync(0xffffffffu, m, s));
    float s1 = (lane < NTILES_L) ? ps[base + lane] * __expf(m1 - m) : 0.f;
    float s2 = (lane + 32 < NTILES_L) ? ps[base + lane + 32] * __expf(m2 - m) : 0.f;
    float ssum = s1 + s2;
    #pragma unroll
    for (int s = 16; s > 0; s >>= 1)
        ssum += __shfl_xor_sync(0xffffffffu, ssum, s);
    if (lane == 0) {
        rowm[row] = m;
        rowinv[row] = 1.f / ssum;
    }
}

// ---------------- f2/f3 small fields: relu(ap @ W + b), channel-last --------
__global__ void f23_kernel(const float* __restrict__ attn,
                           const float* __restrict__ W2, const float* __restrict__ b2,
                           const float* __restrict__ W3, const float* __restrict__ b3,
                           float* __restrict__ f2o, float* __restrict__ f3o)
{
    int bn = blockIdx.y;
    int b = bn / NQ, n = bn % NQ;
    int j = blockIdx.x * blockDim.x + threadIdx.x;
    if (j >= L2SZ + L3SZ) return;

    int lidx = (j < L2SZ) ? (L2OFF + j) : (L3OFF + (j - L2SZ));
    size_t base = ((size_t)(b*HH)*NQ + n)*LTOT + lidx;
    float a[8];
    #pragma unroll
    for (int hh = 0; hh < 8; hh++)
        a[hh] = attn[base + (size_t)hh * NL];

    if (j < L2SZ) {
        float* dst = f2o + ((size_t)bn * L2SZ + j) * 8;
        #pragma unroll
        for (int h = 0; h < 8; h++) {
            float s = b2[h];
            #pragma unroll
            for (int hh = 0; hh < 8; hh++) s = fmaf(a[hh], W2[hh*8 + h], s);
            dst[h] = fmaxf(s, 0.f);
        }
    } else {
        int jj = j - L2SZ;
        float* dst = f3o + ((size_t)bn * L3SZ + jj) * 8;
        #pragma unroll
        for (int h = 0; h < 8; h++) {
            float s = b3[h];
            #pragma unroll
            for (int hh = 0; hh < 8; hh++) s = fmaf(a[hh], W3[hh*8 + h], s);
            dst[h] = fmaxf(s, 0.f);
        }
    }
}

// ---------------- fused mask: f1 + bilinear(f2) + bilinear(f3), dot Wm, relu -
__global__ void mask_kernel(const float* __restrict__ attn,
                            const float* __restrict__ f2f, const float* __restrict__ f3f,
                            const float* __restrict__ W1, const float* __restrict__ b1,
                            const float* __restrict__ Wm, const float* __restrict__ bm,
                            float* __restrict__ outmask)
{
    __shared__ float sW1[64], sb1[8], sWm[24], sbm[1];
    int t = threadIdx.x;
    if (t < 64) sW1[t] = W1[t];
    if (t < 8)  sb1[t] = b1[t];
    if (t < 24) sWm[t] = Wm[t];
    if (t == 0) sbm[0] = bm[0];
    __syncthreads();

    int bn = blockIdx.y;
    int b = bn / NQ, n = bn % NQ;
    int p = blockIdx.x * blockDim.x + t;
    int Y = p >> 6, X = p & 63;

    size_t base = ((size_t)(b*HH)*NQ + n)*LTOT + p;
    float a[8];
    #pragma unroll
    for (int hh = 0; hh < 8; hh++)
        a[hh] = attn[base + (size_t)hh * NL];

    float acc = sbm[0];
    #pragma unroll
    for (int h = 0; h < 8; h++) {
        float s = sb1[h];
        #pragma unroll
        for (int hh = 0; hh < 8; hh++) s = fmaf(a[hh], sW1[hh*8 + h], s);
        acc = fmaf(fmaxf(s, 0.f), sWm[h], acc);
    }

    {   // f2: bilinear from 32x32
        float ry = fminf(fmaxf(0.5f*(float)Y - 0.25f, 0.f), 31.f);
        float rx = fminf(fmaxf(0.5f*(float)X - 0.25f, 0.f), 31.f);
        int y0 = (int)ry, x0 = (int)rx;
        int y1 = min(y0+1, 31), x1 = min(x0+1, 31);
        float wy = ry - (float)y0, wx = rx - (float)x0;
        float w00 = (1.f-wy)*(1.f-wx), w01 = (1.f-wy)*wx, w10 = wy*(1.f-wx), w11 = wy*wx;
        const float* fb = f2f + (size_t)bn * (L2SZ*8);
        const float* t00 = fb + (y0*32 + x0)*8;
        const float* t01 = fb + (y0*32 + x1)*8;
        const float* t10 = fb + (y1*32 + x0)*8;
        const float* t11 = fb + (y1*32 + x1)*8;
        #pragma unroll
        for (int h = 0; h < 8; h++) {
            float v = w00*t00[h] + w01*t01[h] + w10*t10[h] + w11*t11[h];
            acc = fmaf(v, sWm[8 + h], acc);
        }
    }
    {   // f3: bilinear from 16x16
        float ry = fminf(fmaxf(0.25f*(float)Y - 0.375f, 0.f), 15.f);
        float rx = fminf(fmaxf(0.25f*(float)X - 0.375f, 0.f), 15.f);
        int y0 = (int)ry, x0 = (int)rx;
        int y1 = min(y0+1, 15), x1 = min(x0+1, 15);
        float wy = ry - (float)y0, wx = rx - (float)x0;
        float w00 = (1.f-wy)*(1.f-wx), w01 = (1.f-wy)*wx, w10 = wy*(1.f-wx), w11 = wy*wx;
        const float* fb = f3f + (size_t)bn * (L3SZ*8);
        const float* t00 = fb + (y0*16 + x0)*8;
        const float* t01 = fb + (y0*16 + x1)*8;
        const float* t10 = fb + (y1*16 + x0)*8;
        const float* t11 = fb + (y1*16 + x1)*8;
        #pragma unroll
        for (int h = 0; h < 8; h++) {
            float v = w00*t00[h] + w01*t01[h] + w10*t10[h] + w11*t11[h];
            acc = fmaf(v, sWm[16 + h], acc);
        }
    }
    outmask[(size_t)bn * L1SZ + p] = fmaxf(acc, 0.f);
}

// ---------------- zero ----
__global__ void zero_kernel(float* __restrict__ p, int n)
{
    int i = blockIdx.x * blockDim.x + threadIdx.x;
    if (i < n) p[i] = 0.f;
}

// ---------------- AV: probs computed on the fly from raw logits -------------
__global__ void av_kernel(const float* __restrict__ attn, const float* __restrict__ V,
                          const float* __restrict__ rowm, const float* __restrict__ rowinv,
                          float* __restrict__ X)
{
    __shared__ float As[32][68];
    __shared__ float Bs[32][32];
    __shared__ float srm[64], sri[64];
    int tid = threadIdx.x;
    int bh = blockIdx.z;
    int b = bh >> 3, h = bh & 7;
    int nbase = blockIdx.y * 64;
    int l0 = blockIdx.x * 672;
    int tm = (tid >> 4) * 8;
    int tn = (tid & 15) * 2;

    if (tid < 64) {
        int row = nbase + tid;
        bool ok = row < NQ;
        srm[tid] = ok ? rowm[(size_t)bh*NQ + row] : 0.f;
        sri[tid] = ok ? rowinv[(size_t)bh*NQ + row] : 0.f;
    }
    __syncthreads();

    float acc[8][2];
    #pragma unroll
    for (int i = 0; i < 8; i++) { acc[i][0] = 0.f; acc[i][1] = 0.f; }

    for (int k0 = l0; k0 < l0 + 672; k0 += 32) {
        for (int i = tid; i < 64*32; i += 128) {
            int m = i >> 5, kk = i & 31;
            int row = nbase + m;
            float p = 0.f;
            if (row < NQ) {
                float v = attn[((size_t)bh*NQ + row)*LTOT + k0 + kk];
                p = __expf(v - srm[m]) * sri[m];
            }
            As[kk][m] = p;
        }
        for (int i = tid; i < 32*32; i += 128) {
            int kk = i >> 5, d = i & 31;
            Bs[kk][d] = V[((size_t)b*LTOT + k0 + kk)*CC + h*32 + d];
        }
        __syncthreads();
        #pragma unroll
        for (int kk = 0; kk < 32; kk++) {
            float a[8];
            *(float4*)&a[0] = *(const float4*)&As[kk][tm];
            *(float4*)&a[4] = *(const float4*)&As[kk][tm+4];
            float b0 = Bs[kk][tn], b1 = Bs[kk][tn+1];
            #pragma unroll
            for (int i = 0; i < 8; i++) {
                acc[i][0] = fmaf(a[i], b0, acc[i][0]);
                acc[i][1] = fmaf(a[i], b1, acc[i][1]);
            }
        }
        __syncthreads();
    }
    #pragma unroll
    for (int i = 0; i < 8; i++) {
        int row = nbase + tm + i;
        if (row >= NQ) continue;
        atomicAdd(&X[((size_t)b*NQ + row)*CC + h*32 + tn    ], acc[i][0]);
        atomicAdd(&X[((size_t)b*NQ + row)*CC + h*32 + tn + 1], acc[i][1]);
    }
}

// ---------------- launch ----
extern "C" void kernel_launch(void* const* d_in, const int* in_sizes, int n_in,
                              void* d_out, int out_size)
{
    const float* query = (const float*)d_in[0];
    const float* key   = (const float*)d_in[1];
    const float* value = (const float*)d_in[2];
    const float* Wq = (const float*)d_in[5];
    const float* Wk = (const float*)d_in[6];
    const float* Wv = (const float*)d_in[7];
    const float* Wp = (const float*)d_in[8];
    const float* bp = (const float*)d_in[9];
    const float* W1 = (const float*)d_in[10];
    const float* b1 = (const float*)d_in[11];
    const float* W2 = (const float*)d_in[12];
    const float* b2 = (const float*)d_in[13];
    const float* W3 = (const float*)d_in[14];
    const float* b3 = (const float*)d_in[15];
    const float* Wm = (const float*)d_in[16];
    const float* bm = (const float*)d_in[17];

    float* out_x    = (float*)d_out;
    float* out_mask = (float*)d_out + BB*NQ*CC;

    float *gq, *gk, *gv, *gattn, *gf2, *gf3, *gx, *gpm, *gps, *grm, *gri;
    __nv_bfloat16 *gkimg, *gvimg, *gwk, *gwv;
    cudaGetSymbolAddress((void**)&gq,    g_q);
    cudaGetSymbolAddress((void**)&gk,    g_k);
    cudaGetSymbolAddress((void**)&gv,    g_v);
    cudaGetSymbolAddress((void**)&gattn, g_attn);
    cudaGetSymbolAddress((void**)&gf2,   g_f2);
    cudaGetSymbolAddress((void**)&gf3,   g_f3);
    cudaGetSymbolAddress((void**)&gx,    g_x);
    cudaGetSymbolAddress((void**)&gpm,   g_pm);
    cudaGetSymbolAddress((void**)&gps,   g_ps);
    cudaGetSymbolAddress((void**)&grm,   g_rowm);
    cudaGetSymbolAddress((void**)&gri,   g_rowinv);
    cudaGetSymbolAddress((void**)&gkimg, g_kimg);
    cudaGetSymbolAddress((void**)&gvimg, g_vimg);
    cudaGetSymbolAddress((void**)&gwk,   g_wk);
    cudaGetSymbolAddress((void**)&gwv,   g_wv);

    const int PROJ_SMEM = 3 * 128 * PSTR * 2;   // 55296 B
    cudaFuncSetAttribute(proj_mma_kernel, cudaFuncAttributeMaxDynamicSharedMemorySize, PROJ_SMEM);

    // 1a) split-precision images
    prep_split_kernel<<<(MKV*64 + 255)/256, 256>>>(key,   gkimg, MKV);
    prep_split_kernel<<<(MKV*64 + 255)/256, 256>>>(value, gvimg, MKV);
    prep_wt_kernel<<<256, 256>>>(Wk, gwk);
    prep_wt_kernel<<<256, 256>>>(Wv, gwv);

    // 1b) K/V projections on tensor cores (mma.sync bf16 hi/lo split)
    proj_mma_kernel<<<dim3(2, 84), 256, PROJ_SMEM>>>(gkimg, gwk, gk);
    proj_mma_kernel<<<dim3(2, 84), 256, PROJ_SMEM>>>(gvimg, gwv, gv);

    // 1c) Q projection (small) on fp32 path
    proj_gemm_kernel<<<dim3(4, 10), 128>>>(query, Wq, nullptr, gq, BB*NQ);

    // 2) attention logits + per-tile softmax partials
    attn_gemm_kernel<<<dim3(NTILES_L, 5, 16), 256>>>(gq, gk, gattn, gpm, gps);

    // 3) per-row softmax stats
    softstats_kernel<<<NROWS/8, 256>>>(gpm, gps, grm, gri);

    // 4) mask path (reads raw logits)
    f23_kernel<<<dim3(5, 600), 256>>>(gattn, W2, b2, W3, b3, gf2, gf3);
    mask_kernel<<<dim3(32, 600), 128>>>(gattn, gf2, gf3, W1, b1, Wm, bm, out_mask);

    // 5) AV with on-the-fly normalization, 8-way L split
    zero_kernel<<<(BB*NQ*CC + 255)/256, 256>>>(gx, BB*NQ*CC);
    av_kernel<<<dim3(8, 5, 16), 128>>>(gattn, gv, grm, gri, gx);

    // 6) output projection
    proj_gemm_kernel<<<dim3(4, 10), 128>>>(gx, Wp, bp, out_x, BB*NQ);
}

// round 15
// speedup vs baseline: 1.5558x; 1.0908x over previous
#include <cuda_runtime.h>
#include <cuda_bf16.h>
#include <cstdint>
#include <math.h>

// Problem constants
#define BB 2
#define NQ 300
#define CC 256
#define HH 8
#define DD 32
#define LTOT 5376
#define L1SZ 4096   // 64x64
#define L2OFF 4096
#define L2SZ 1024   // 32x32
#define L3OFF 5120
#define L3SZ 256    // 16x16
#define NL (NQ*LTOT)            // 1,612,800
#define NT2 84                  // 64-col softmax partial tiles per row (5376/64)
#define NROWS (BB*HH*NQ)        // 4800
#define MKV (BB*LTOT)           // 10752 rows for K/V projections
#define QPAD 384                // padded query rows per (b,h) for 128-tiles
#define SCALE 0.17677669529663687f  // 1/sqrt(32)

// ---------------- scratch (device globals; allocation-free) ----------------
__device__ float g_q[BB*NQ*CC];
__device__ float g_v[BB*LTOT*CC];
__device__ float g_attn[(size_t)BB*HH*NQ*LTOT];   // raw scaled logits
__device__ float g_f2[BB*NQ*L2SZ*HH];
__device__ float g_f3[BB*NQ*L3SZ*HH];
__device__ float g_x[BB*NQ*CC];
__device__ float g_pm[(size_t)NROWS*NT2];
__device__ float g_ps[(size_t)NROWS*NT2];
__device__ float g_rowm[NROWS];
__device__ float g_rowinv[NROWS];
__device__ __nv_bfloat16 g_kimg[(size_t)MKV*512];       // key   input hi|lo split [r][512]
__device__ __nv_bfloat16 g_vimg[(size_t)MKV*512];       // value input hi|lo split
__device__ __nv_bfloat16 g_wk[256*512];                 // Wk^T hi|lo image [n][512]
__device__ __nv_bfloat16 g_wv[256*512];                 // Wv^T hi|lo image
__device__ __nv_bfloat16 g_kh[(size_t)BB*HH*LTOT*64];   // projected K head image [bh][l][hi32|lo32]
__device__ __nv_bfloat16 g_qh[(size_t)BB*HH*QPAD*64];   // projected Q head image [bh][row][hi32|lo32]

// ================= mma.sync helpers =================
__device__ __forceinline__ uint32_t smem_u32(const void* p) {
    uint32_t a;
    asm("{ .reg .u64 t; cvta.to.shared.u64 t, %1; cvt.u32.u64 %0, t; }" : "=r"(a) : "l"(p));
    return a;
}
#define LDSM4(r, addr) \
    asm volatile("ldmatrix.sync.aligned.m8n8.x4.shared.b16 {%0,%1,%2,%3}, [%4];" \
        : "=r"((r)[0]), "=r"((r)[1]), "=r"((r)[2]), "=r"((r)[3]) : "r"(addr))
#define MMA16816(dd, aa, b0, b1) \
    asm volatile("mma.sync.aligned.m16n8k16.row.col.f32.bf16.bf16.f32 " \
        "{%0,%1,%2,%3},{%4,%5,%6,%7},{%8,%9},{%0,%1,%2,%3};" \
        : "+f"((dd)[0]), "+f"((dd)[1]), "+f"((dd)[2]), "+f"((dd)[3]) \
        : "r"((aa)[0]), "r"((aa)[1]), "r"((aa)[2]), "r"((aa)[3]), "r"(b0), "r"(b1))

// ---------------- prep: split fp32 rows into [hi(256)|lo(256)] bf16 image ----
__global__ void prep_split_kernel(const float* __restrict__ A, __nv_bfloat16* __restrict__ img,
                                  int M)
{
    int idx = blockIdx.x * blockDim.x + threadIdx.x;
    if (idx >= M * 64) return;
    int r = idx >> 6, c4 = (idx & 63) * 4;
    float4 v = *(const float4*)(A + (size_t)r * 256 + c4);
    __nv_bfloat16 hi[4], lo[4];
    hi[0] = __float2bfloat16(v.x); lo[0] = __float2bfloat16(v.x - __bfloat162float(hi[0]));
    hi[1] = __float2bfloat16(v.y); lo[1] = __float2bfloat16(v.y - __bfloat162float(hi[1]));
    hi[2] = __float2bfloat16(v.z); lo[2] = __float2bfloat16(v.z - __bfloat162float(hi[2]));
    hi[3] = __float2bfloat16(v.w); lo[3] = __float2bfloat16(v.w - __bfloat162float(hi[3]));
    *(uint2*)(img + (size_t)r * 512 + c4)       = *(uint2*)hi;
    *(uint2*)(img + (size_t)r * 512 + 256 + c4) = *(uint2*)lo;
}

// ---------------- prep: W[k][n] -> Wt image [n][ hi k(256) | lo k(256) ] ----
__global__ void prep_wt_kernel(const float* __restrict__ W, __nv_bfloat16* __restrict__ img)
{
    int n = blockIdx.x;
    int k = threadIdx.x;
    float x = W[(size_t)k * 256 + n];
    __nv_bfloat16 h = __float2bfloat16(x);
    img[(size_t)n * 512 + k]       = h;
    img[(size_t)n * 512 + 256 + k] = __float2bfloat16(x - __bfloat162float(h));
}

// ---------------- prep: q fp32 -> padded head-split image [bh][row<384][64] --
__global__ void prep_q_kernel(const float* __restrict__ Q, __nv_bfloat16* __restrict__ img)
{
    int idx = blockIdx.x * blockDim.x + threadIdx.x;   // 16*384*32 = 196608
    if (idx >= BB*HH*QPAD*32) return;
    int c   = idx & 31;
    int row = (idx >> 5) % QPAD;
    int bh  = idx / (QPAD * 32);
    int b = bh >> 3, h = bh & 7;
    float x = (row < NQ) ? Q[((size_t)b*NQ + row)*CC + h*32 + c] : 0.f;
    __nv_bfloat16 hi = __float2bfloat16(x);
    __nv_bfloat16* dst = img + ((size_t)bh * QPAD + row) * 64;
    dst[c]      = hi;
    dst[32 + c] = __float2bfloat16(x - __bfloat162float(hi));
}

// ---------------- tensor-core projection: C = A @ W via bf16 split ----------
// mode 0: write fp32 rows to Cout.  mode 1: write bf16 head-split image to Hout.
#define PSTR 72
__global__ void __launch_bounds__(256)
proj_mma_kernel(const __nv_bfloat16* __restrict__ Aimg, const __nv_bfloat16* __restrict__ Wimg,
                float* __restrict__ Cout, __nv_bfloat16* __restrict__ Hout, int mode)
{
    extern __shared__ __align__(16) char dsm[];
    __nv_bfloat16* sA  = (__nv_bfloat16*)dsm;
    __nv_bfloat16* sB1 = (__nv_bfloat16*)(dsm + 128*PSTR*2);
    __nv_bfloat16* sB2 = (__nv_bfloat16*)(dsm + 2*128*PSTR*2);
    const int tid = threadIdx.x;
    const int lane = tid & 31, wid = tid >> 5;
    const int wm = (wid & 3) * 32;
    const int wn = (wid >> 2) * 64;
    const int m0 = blockIdx.y * 128;
    const int n0 = blockIdx.x * 128;

    float d[2][8][4];
    #pragma unroll
    for (int i = 0; i < 2; i++)
        #pragma unroll
        for (int j = 0; j < 8; j++)
            #pragma unroll
            for (int q = 0; q < 4; q++) d[i][j][q] = 0.f;

    const uint32_t sa_u = smem_u32(sA), sb1_u = smem_u32(sB1), sb2_u = smem_u32(sB2);

    for (int kc = 0; kc < 512; kc += 64) {
        int kc2 = (kc + 256) & 511;
        for (int i = tid; i < 1024; i += 256) {
            int r = i >> 3, c = i & 7;
            *(uint4*)(sA + r * PSTR + c * 8) =
                *(const uint4*)(Aimg + (size_t)(m0 + r) * 512 + kc + c * 8);
        }
        for (int i = tid; i < 1024; i += 256) {
            int r = i >> 3, c = i & 7;
            const __nv_bfloat16* wrow = Wimg + (size_t)(n0 + r) * 512;
            *(uint4*)(sB1 + r * PSTR + c * 8) = *(const uint4*)(wrow + kc  + c * 8);
            *(uint4*)(sB2 + r * PSTR + c * 8) = *(const uint4*)(wrow + kc2 + c * 8);
        }
        __syncthreads();
        #pragma unroll
        for (int ks = 0; ks < 4; ks++) {
            uint32_t a[2][4];
            #pragma unroll
            for (int am = 0; am < 2; am++) {
                uint32_t addr = sa_u +
                    ((uint32_t)((wm + am*16 + (lane & 15)) * PSTR + ks*16 + (lane >> 4)*8) << 1);
                LDSM4(a[am], addr);
            }
            #pragma unroll
            for (int p = 0; p < 4; p++) {
                uint32_t boff = ((uint32_t)((wn + p*16 + (lane & 7) + ((lane >> 4) << 3)) * PSTR
                                 + ks*16 + ((lane >> 3) & 1) * 8) << 1);
                uint32_t b[4];
                LDSM4(b, sb1_u + boff);
                MMA16816(d[0][2*p],   a[0], b[0], b[1]);
                MMA16816(d[0][2*p+1], a[0], b[2], b[3]);
                MMA16816(d[1][2*p],   a[1], b[0], b[1]);
                MMA16816(d[1][2*p+1], a[1], b[2], b[3]);
                LDSM4(b, sb2_u + boff);
                MMA16816(d[0][2*p],   a[0], b[0], b[1]);
                MMA16816(d[0][2*p+1], a[0], b[2], b[3]);
                MMA16816(d[1][2*p],   a[1], b[0], b[1]);
                MMA16816(d[1][2*p+1], a[1], b[2], b[3]);
            }
        }
        __syncthreads();
    }

    if (mode == 0) {
        #pragma unroll
        for (int am = 0; am < 2; am++) {
            int rbase = m0 + wm + am * 16 + (lane >> 2);
            #pragma unroll
            for (int na = 0; na < 8; na++) {
                int col = n0 + wn + na * 8 + (lane & 3) * 2;
                float* p0 = Cout + (size_t)rbase * 256 + col;
                p0[0] = d[am][na][0]; p0[1] = d[am][na][1];
                float* p1 = Cout + (size_t)(rbase + 8) * 256 + col;
                p1[0] = d[am][na][2]; p1[1] = d[am][na][3];
            }
        }
    } else {
        // head-split bf16 image: [b*HH+h][l][hi c | lo c]
        #pragma unroll
        for (int am = 0; am < 2; am++) {
            int r0 = m0 + wm + am * 16 + (lane >> 2);
            #pragma unroll
            for (int rr = 0; rr < 2; rr++) {
                int r = r0 + rr * 8;
                int b = r / LTOT, l = r - b * LTOT;
                #pragma unroll
                for (int na = 0; na < 8; na++) {
                    int col = n0 + wn + na * 8 + (lane & 3) * 2;
                    int h = col >> 5, c = col & 31;
                    __nv_bfloat16* dst = Hout + ((size_t)(b*HH + h)*LTOT + l)*64;
                    float x0 = d[am][na][rr*2], x1 = d[am][na][rr*2 + 1];
                    __nv_bfloat16 h0 = __float2bfloat16(x0);
                    __nv_bfloat16 h1 = __float2bfloat16(x1);
                    __nv_bfloat16 v2[2];
                    v2[0] = h0; v2[1] = h1;
                    *(uint32_t*)(dst + c) = *(uint32_t*)v2;
                    v2[0] = __float2bfloat16(x0 - __bfloat162float(h0));
                    v2[1] = __float2bfloat16(x1 - __bfloat162float(h1));
                    *(uint32_t*)(dst + 32 + c) = *(uint32_t*)v2;
                }
            }
        }
    }
}

// ---------------- attention logits on tensor cores + softmax partials -------
// grid (42 l-tiles, 3 m-tiles, 16 bh), 256 threads; K'=64 hi|lo with cross terms
__global__ void __launch_bounds__(256)
attn_mma_kernel(const __nv_bfloat16* __restrict__ Qimg, const __nv_bfloat16* __restrict__ Kimg,
                float* __restrict__ attn, float* __restrict__ pm, float* __restrict__ ps)
{
    __shared__ __align__(16) __nv_bfloat16 sA[128*PSTR];
    __shared__ __align__(16) __nv_bfloat16 sB[128*PSTR];
    const int tid = threadIdx.x;
    const int lane = tid & 31, wid = tid >> 5;
    const int wm = (wid & 3) * 32;
    const int wn = (wid >> 2) * 64;
    const int bh = blockIdx.z;
    const int m0 = blockIdx.y * 128;
    const int l0 = blockIdx.x * 128;

    for (int i = tid; i < 1024; i += 256) {
        int r = i >> 3, c = i & 7;
        *(uint4*)(sA + r * PSTR + c * 8) =
            *(const uint4*)(Qimg + ((size_t)bh * QPAD + m0 + r) * 64 + c * 8);
    }
    for (int i = tid; i < 1024; i += 256) {
        int r = i >> 3, c = i & 7;
        *(uint4*)(sB + r * PSTR + c * 8) =
            *(const uint4*)(Kimg + ((size_t)bh * LTOT + l0 + r) * 64 + c * 8);
    }
    __syncthreads();

    const uint32_t sa_u = smem_u32(sA), sb_u = smem_u32(sB);
    float d[2][8][4];
    #pragma unroll
    for (int i = 0; i < 2; i++)
        #pragma unroll
        for (int j = 0; j < 8; j++)
            #pragma unroll
            for (int q = 0; q < 4; q++) d[i][j][q] = 0.f;

    #pragma unroll
    for (int ks = 0; ks < 4; ks++) {
        int ksx = ks ^ 2;   // swapped-half index for cross terms
        uint32_t a[2][4];
        #pragma unroll
        for (int am = 0; am < 2; am++) {
            uint32_t addr = sa_u +
                ((uint32_t)((wm + am*16 + (lane & 15)) * PSTR + ks*16 + (lane >> 4)*8) << 1);
            LDSM4(a[am], addr);
        }
        #pragma unroll
        for (int p = 0; p < 4; p++) {
            uint32_t rowterm = (uint32_t)((wn + p*16 + (lane & 7) + ((lane >> 4) << 3)) * PSTR
                               + ((lane >> 3) & 1) * 8);
            uint32_t b[4];
            // direct: q_half(ks) · k_half(ks)  (hi·hi + lo·lo across ks loop)
            LDSM4(b, sb_u + ((rowterm + ks*16) << 1));
            MMA16816(d[0][2*p],   a[0], b[0], b[1]);
            MMA16816(d[0][2*p+1], a[0], b[2], b[3]);
            MMA16816(d[1][2*p],   a[1], b[0], b[1]);
            MMA16816(d[1][2*p+1], a[1], b[2], b[3]);
            // cross: q_half(ks) · k_half(ks^2)  (hi·lo + lo·hi across ks loop)
            LDSM4(b, sb_u + ((rowterm + ksx*16) << 1));
            MMA16816(d[0][2*p],   a[0], b[0], b[1]);
            MMA16816(d[0][2*p+1], a[0], b[2], b[3]);
            MMA16816(d[1][2*p],   a[1], b[0], b[1]);
            MMA16816(d[1][2*p+1], a[1], b[2], b[3]);
        }
    }

    // epilogue: scale, store logits, per-row (max, sumexp) over this 64-col span
    int tileIdx = blockIdx.x * 2 + (wn >> 6);
    #pragma unroll
    for (int am = 0; am < 2; am++) {
        int r0 = m0 + wm + am * 16 + (lane >> 2);
        #pragma unroll
        for (int q = 0; q < 4; q++)
            #pragma unroll
            for (int na = 0; na < 8; na++) d[am][na][q] *= SCALE;

        #pragma unroll
        for (int rr = 0; rr < 2; rr++) {
            int row = r0 + rr * 8;
            bool ok = row < NQ;
            float v0max = -1e30f, sum = 0.f;
            #pragma unroll
            for (int na = 0; na < 8; na++) {
                float x0 = d[am][na][rr*2], x1 = d[am][na][rr*2+1];
                v0max = fmaxf(v0max, fmaxf(x0, x1));
            }
            v0max = fmaxf(v0max, __shfl_xor_sync(0xffffffffu, v0max, 1));
            v0max = fmaxf(v0max, __shfl_xor_sync(0xffffffffu, v0max, 2));
            #pragma unroll
            for (int na = 0; na < 8; na++) {
                float x0 = d[am][na][rr*2], x1 = d[am][na][rr*2+1];
                sum += __expf(x0 - v0max) + __expf(x1 - v0max);
                if (ok) {
                    float2 o; o.x = x0; o.y = x1;
                    *(float2*)&attn[((size_t)bh*NQ + row)*LTOT + l0 + wn + na*8 + (lane & 3)*2] = o;
                }
            }
            sum += __shfl_xor_sync(0xffffffffu, sum, 1);
            sum += __shfl_xor_sync(0xffffffffu, sum, 2);
            if (ok && (lane & 3) == 0) {
                size_t pidx = ((size_t)bh*NQ + row)*NT2 + tileIdx;
                pm[pidx] = v0max;
                ps[pidx] = sum;
            }
        }
    }
}

// ---------------- projection GEMM (small M): C[M,256] = A @ W (+bias) ----------
__global__ void proj_gemm_kernel(const float* __restrict__ A, const float* __restrict__ W,
                                 const float* __restrict__ bias, float* __restrict__ Cout,
                                 int M)
{
    __shared__ float As[16][68];
    __shared__ float Bs[16][68];
    int tid = threadIdx.x;
    int bm = blockIdx.y * 64;
    int bn = blockIdx.x * 64;
    int tm = (tid >> 4) * 8;
    int tn = (tid & 15) * 4;
    float acc[8][4];
    #pragma unroll
    for (int i = 0; i < 8; i++)
        #pragma unroll
        for (int j = 0; j < 4; j++) acc[i][j] = 0.f;

    for (int k0 = 0; k0 < 256; k0 += 16) {
        for (int i = tid; i < 64*16; i += 128) {
            int m = i >> 4, kk = i & 15;
            int row = bm + m;
            As[kk][m] = (row < M) ? A[(size_t)row*256 + k0 + kk] : 0.f;
        }
        for (int i = tid; i < 16*64; i += 128) {
            int kk = i >> 6, n = i & 63;
            Bs[kk][n] = W[(k0 + kk)*256 + bn + n];
        }
        __syncthreads();
        #pragma unroll
        for (int kk = 0; kk < 16; kk++) {
            float a[8], bb[4];
            *(float4*)&a[0] = *(const float4*)&As[kk][tm];
            *(float4*)&a[4] = *(const float4*)&As[kk][tm+4];
            *(float4*)&bb[0] = *(const float4*)&Bs[kk][tn];
            #pragma unroll
            for (int i = 0; i < 8; i++)
                #pragma unroll
                for (int j = 0; j < 4; j++)
                    acc[i][j] = fmaf(a[i], bb[j], acc[i][j]);
        }
        __syncthreads();
    }
    #pragma unroll
    for (int i = 0; i < 8; i++) {
        int row = bm + tm + i;
        if (row >= M) continue;
        #pragma unroll
        for (int j = 0; j < 4; j++) {
            float v = acc[i][j];
            if (bias) v += bias[bn + tn + j];
            Cout[(size_t)row*256 + bn + tn + j] = v;
        }
    }
}

// ---------------- combine per-tile partials into per-row (max, 1/sum) -------
__global__ void softstats_kernel(const float* __restrict__ pm, const float* __restrict__ ps,
                                 float* __restrict__ rowm, float* __restrict__ rowinv)
{
    int row = blockIdx.x * 8 + (threadIdx.x >> 5);
    int lane = threadIdx.x & 31;
    size_t base = (size_t)row * NT2;
    float m = -1e30f;
    for (int i = lane; i < NT2; i += 32) m = fmaxf(m, pm[base + i]);
    #pragma unroll
    for (int s = 16; s > 0; s >>= 1)
        m = fmaxf(m, __shfl_xor_sync(0xffffffffu, m, s));
    float ssum = 0.f;
    for (int i = lane; i < NT2; i += 32) ssum += ps[base + i] * __expf(pm[base + i] - m);
    #pragma unroll
    for (int s = 16; s > 0; s >>= 1)
        ssum += __shfl_xor_sync(0xffffffffu, ssum, s);
    if (lane == 0) {
        rowm[row] = m;
        rowinv[row] = 1.f / ssum;
    }
}

// ---------------- f2/f3 small fields: relu(ap @ W + b), channel-last --------
__global__ void f23_kernel(const float* __restrict__ attn,
                           const float* __restrict__ W2, const float* __restrict__ b2,
                           const float* __restrict__ W3, const float* __restrict__ b3,
                           float* __restrict__ f2o, float* __restrict__ f3o)
{
    int bn = blockIdx.y;
    int b = bn / NQ, n = bn % NQ;
    int j = blockIdx.x * blockDim.x + threadIdx.x;
    if (j >= L2SZ + L3SZ) return;

    int lidx = (j < L2SZ) ? (L2OFF + j) : (L3OFF + (j - L2SZ));
    size_t base = ((size_t)(b*HH)*NQ + n)*LTOT + lidx;
    float a[8];
    #pragma unroll
    for (int hh = 0; hh < 8; hh++)
        a[hh] = attn[base + (size_t)hh * NL];

    if (j < L2SZ) {
        float* dst = f2o + ((size_t)bn * L2SZ + j) * 8;
        #pragma unroll
        for (int h = 0; h < 8; h++) {
            float s = b2[h];
            #pragma unroll
            for (int hh = 0; hh < 8; hh++) s = fmaf(a[hh], W2[hh*8 + h], s);
            dst[h] = fmaxf(s, 0.f);
        }
    } else {
        int jj = j - L2SZ;
        float* dst = f3o + ((size_t)bn * L3SZ + jj) * 8;
        #pragma unroll
        for (int h = 0; h < 8; h++) {
            float s = b3[h];
            #pragma unroll
            for (int hh = 0; hh < 8; hh++) s = fmaf(a[hh], W3[hh*8 + h], s);
            dst[h] = fmaxf(s, 0.f);
        }
    }
}

// ---------------- fused mask: f1 + bilinear(f2) + bilinear(f3), dot Wm, relu -
__global__ void mask_kernel(const float* __restrict__ attn,
                            const float* __restrict__ f2f, const float* __restrict__ f3f,
                            const float* __restrict__ W1, const float* __restrict__ b1,
                            const float* __restrict__ Wm, const float* __restrict__ bm,
                            float* __restrict__ outmask)
{
    __shared__ float sW1[64], sb1[8], sWm[24], sbm[1];
    int t = threadIdx.x;
    if (t < 64) sW1[t] = W1[t];
    if (t < 8)  sb1[t] = b1[t];
    if (t < 24) sWm[t] = Wm[t];
    if (t == 0) sbm[0] = bm[0];
    __syncthreads();

    int bn = blockIdx.y;
    int b = bn / NQ, n = bn % NQ;
    int p = blockIdx.x * blockDim.x + t;
    int Y = p >> 6, X = p & 63;

    size_t base = ((size_t)(b*HH)*NQ + n)*LTOT + p;
    float a[8];
    #pragma unroll
    for (int hh = 0; hh < 8; hh++)
        a[hh] = attn[base + (size_t)hh * NL];

    float acc = sbm[0];
    #pragma unroll
    for (int h = 0; h < 8; h++) {
        float s = sb1[h];
        #pragma unroll
        for (int hh = 0; hh < 8; hh++) s = fmaf(a[hh], sW1[hh*8 + h], s);
        acc = fmaf(fmaxf(s, 0.f), sWm[h], acc);
    }

    {   // f2: bilinear from 32x32
        float ry = fminf(fmaxf(0.5f*(float)Y - 0.25f, 0.f), 31.f);
        float rx = fminf(fmaxf(0.5f*(float)X - 0.25f, 0.f), 31.f);
        int y0 = (int)ry, x0 = (int)rx;
        int y1 = min(y0+1, 31), x1 = min(x0+1, 31);
        float wy = ry - (float)y0, wx = rx - (float)x0;
        float w00 = (1.f-wy)*(1.f-wx), w01 = (1.f-wy)*wx, w10 = wy*(1.f-wx), w11 = wy*wx;
        const float* fb = f2f + (size_t)bn * (L2SZ*8);
        const float* t00 = fb + (y0*32 + x0)*8;
        const float* t01 = fb + (y0*32 + x1)*8;
        const float* t10 = fb + (y1*32 + x0)*8;
        const float* t11 = fb + (y1*32 + x1)*8;
        #pragma unroll
        for (int h = 0; h < 8; h++) {
            float v = w00*t00[h] + w01*t01[h] + w10*t10[h] + w11*t11[h];
            acc = fmaf(v, sWm[8 + h], acc);
        }
    }
    {   // f3: bilinear from 16x16
        float ry = fminf(fmaxf(0.25f*(float)Y - 0.375f, 0.f), 15.f);
        float rx = fminf(fmaxf(0.25f*(float)X - 0.375f, 0.f), 15.f);
        int y0 = (int)ry, x0 = (int)rx;
        int y1 = min(y0+1, 15), x1 = min(x0+1, 15);
        float wy = ry - (float)y0, wx = rx - (float)x0;
        float w00 = (1.f-wy)*(1.f-wx), w01 = (1.f-wy)*wx, w10 = wy*(1.f-wx), w11 = wy*wx;
        const float* fb = f3f + (size_t)bn * (L3SZ*8);
        const float* t00 = fb + (y0*16 + x0)*8;
        const float* t01 = fb + (y0*16 + x1)*8;
        const float* t10 = fb + (y1*16 + x0)*8;
        const float* t11 = fb + (y1*16 + x1)*8;
        #pragma unroll
        for (int h = 0; h < 8; h++) {
            float v = w00*t00[h] + w01*t01[h] + w10*t10[h] + w11*t11[h];
            acc = fmaf(v, sWm[16 + h], acc);
        }
    }
    outmask[(size_t)bn * L1SZ + p] = fmaxf(acc, 0.f);
}

// ---------------- zero ----
__global__ void zero_kernel(float* __restrict__ p, int n)
{
    int i = blockIdx.x * blockDim.x + threadIdx.x;
    if (i < n) p[i] = 0.f;
}

// ---------------- AV: probs computed on the fly from raw logits -------------
__global__ void av_kernel(const float* __restrict__ attn, const float* __restrict__ V,
                          const float* __restrict__ rowm, const float* __restrict__ rowinv,
                          float* __restrict__ X)
{
    __shared__ float As[32][68];
    __shared__ float Bs[32][32];
    __shared__ float srm[64], sri[64];
    int tid = threadIdx.x;
    int bh = blockIdx.z;
    int b = bh >> 3, h = bh & 7;
    int nbase = blockIdx.y * 64;
    int l0 = blockIdx.x * 672;
    int tm = (tid >> 4) * 8;
    int tn = (tid & 15) * 2;

    if (tid < 64) {
        int row = nbase + tid;
        bool ok = row < NQ;
        srm[tid] = ok ? rowm[(size_t)bh*NQ + row] : 0.f;
        sri[tid] = ok ? rowinv[(size_t)bh*NQ + row] : 0.f;
    }
    __syncthreads();

    float acc[8][2];
    #pragma unroll
    for (int i = 0; i < 8; i++) { acc[i][0] = 0.f; acc[i][1] = 0.f; }

    for (int k0 = l0; k0 < l0 + 672; k0 += 32) {
        for (int i = tid; i < 64*32; i += 128) {
            int m = i >> 5, kk = i & 31;
            int row = nbase + m;
            float p = 0.f;
            if (row < NQ) {
                float v = attn[((size_t)bh*NQ + row)*LTOT + k0 + kk];
                p = __expf(v - srm[m]) * sri[m];
            }
            As[kk][m] = p;
        }
        for (int i = tid; i < 32*32; i += 128) {
            int kk = i >> 5, d = i & 31;
            Bs[kk][d] = V[((size_t)b*LTOT + k0 + kk)*CC + h*32 + d];
        }
        __syncthreads();
        #pragma unroll
        for (int kk = 0; kk < 32; kk++) {
            float a[8];
            *(float4*)&a[0] = *(const float4*)&As[kk][tm];
            *(float4*)&a[4] = *(const float4*)&As[kk][tm+4];
            float b0 = Bs[kk][tn], b1 = Bs[kk][tn+1];
            #pragma unroll
            for (int i = 0; i < 8; i++) {
                acc[i][0] = fmaf(a[i], b0, acc[i][0]);
                acc[i][1] = fmaf(a[i], b1, acc[i][1]);
            }
        }
        __syncthreads();
    }
    #pragma unroll
    for (int i = 0; i < 8; i++) {
        int row = nbase + tm + i;
        if (row >= NQ) continue;
        atomicAdd(&X[((size_t)b*NQ + row)*CC + h*32 + tn    ], acc[i][0]);
        atomicAdd(&X[((size_t)b*NQ + row)*CC + h*32 + tn + 1], acc[i][1]);
    }
}

// ---------------- launch ----
extern "C" void kernel_launch(void* const* d_in, const int* in_sizes, int n_in,
                              void* d_out, int out_size)
{
    const float* query = (const float*)d_in[0];
    const float* key   = (const float*)d_in[1];
    const float* value = (const float*)d_in[2];
    const float* Wq = (const float*)d_in[5];
    const float* Wk = (const float*)d_in[6];
    const float* Wv = (const float*)d_in[7];
    const float* Wp = (const float*)d_in[8];
    const float* bp = (const float*)d_in[9];
    const float* W1 = (const float*)d_in[10];
    const float* b1 = (const float*)d_in[11];
    const float* W2 = (const float*)d_in[12];
    const float* b2 = (const float*)d_in[13];
    const float* W3 = (const float*)d_in[14];
    const float* b3 = (const float*)d_in[15];
    const float* Wm = (const float*)d_in[16];
    const float* bm = (const float*)d_in[17];

    float* out_x    = (float*)d_out;
    float* out_mask = (float*)d_out + BB*NQ*CC;

    float *gq, *gv, *gattn, *gf2, *gf3, *gx, *gpm, *gps, *grm, *gri;
    __nv_bfloat16 *gkimg, *gvimg, *gwk, *gwv, *gkh, *gqh;
    cudaGetSymbolAddress((void**)&gq,    g_q);
    cudaGetSymbolAddress((void**)&gv,    g_v);
    cudaGetSymbolAddress((void**)&gattn, g_attn);
    cudaGetSymbolAddress((void**)&gf2,   g_f2);
    cudaGetSymbolAddress((void**)&gf3,   g_f3);
    cudaGetSymbolAddress((void**)&gx,    g_x);
    cudaGetSymbolAddress((void**)&gpm,   g_pm);
    cudaGetSymbolAddress((void**)&gps,   g_ps);
    cudaGetSymbolAddress((void**)&grm,   g_rowm);
    cudaGetSymbolAddress((void**)&gri,   g_rowinv);
    cudaGetSymbolAddress((void**)&gkimg, g_kimg);
    cudaGetSymbolAddress((void**)&gvimg, g_vimg);
    cudaGetSymbolAddress((void**)&gwk,   g_wk);
    cudaGetSymbolAddress((void**)&gwv,   g_wv);
    cudaGetSymbolAddress((void**)&gkh,   g_kh);
    cudaGetSymbolAddress((void**)&gqh,   g_qh);

    const int PROJ_SMEM = 3 * 128 * PSTR * 2;
    cudaFuncSetAttribute(proj_mma_kernel, cudaFuncAttributeMaxDynamicSharedMemorySize, PROJ_SMEM);

    // 1a) split-precision input images
    prep_split_kernel<<<(MKV*64 + 255)/256, 256>>>(key,   gkimg, MKV);
    prep_split_kernel<<<(MKV*64 + 255)/256, 256>>>(value, gvimg, MKV);
    prep_wt_kernel<<<256, 256>>>(Wk, gwk);
    prep_wt_kernel<<<256, 256>>>(Wv, gwv);

    // 1b) K/V projections on tensor cores; K writes head-split bf16 image directly
    proj_mma_kernel<<<dim3(2, 84), 256, PROJ_SMEM>>>(gkimg, gwk, nullptr, gkh, 1);
    proj_mma_kernel<<<dim3(2, 84), 256, PROJ_SMEM>>>(gvimg, gwv, gv, nullptr, 0);

    // 1c) Q projection (small fp32) + head-split padded image
    proj_gemm_kernel<<<dim3(4, 10), 128>>>(query, Wq, nullptr, gq, BB*NQ);
    prep_q_kernel<<<(BB*HH*QPAD*32 + 255)/256, 256>>>(gq, gqh);

    // 2) attention logits on tensor cores (with cross terms) + softmax partials
    attn_mma_kernel<<<dim3(NT2/2, 3, BB*HH), 256>>>(gqh, gkh, gattn, gpm, gps);

    // 3) per-row softmax stats
    softstats_kernel<<<NROWS/8, 256>>>(gpm, gps, grm, gri);

    // 4) mask path (reads raw logits)
    f23_kernel<<<dim3(5, 600), 256>>>(gattn, W2, b2, W3, b3, gf2, gf3);
    mask_kernel<<<dim3(32, 600), 128>>>(gattn, gf2, gf3, W1, b1, Wm, bm, out_mask);

    // 5) AV with on-the-fly normalization, 8-way L split
    zero_kernel<<<(BB*NQ*CC + 255)/256, 256>>>(gx, BB*NQ*CC);
    av_kernel<<<dim3(8, 5, 16), 128>>>(gattn, gv, grm, gri, gx);

    // 6) output projection
    proj_gemm_kernel<<<dim3(4, 10), 128>>>(gx, Wp, bp, out_x, BB*NQ);
}

// round 16
// speedup vs baseline: 2.0276x; 1.3033x over previous
#include <cuda_runtime.h>
#include <cuda_bf16.h>
#include <cstdint>
#include <math.h>

// Problem constants
#define BB 2
#define NQ 300
#define CC 256
#define HH 8
#define DD 32
#define LTOT 5376
#define L1SZ 4096   // 64x64
#define L2OFF 4096
#define L2SZ 1024   // 32x32
#define L3OFF 5120
#define L3SZ 256    // 16x16
#define NL (NQ*LTOT)            // 1,612,800
#define NT2 84                  // 64-col softmax partial tiles per row (5376/64)
#define NROWS (BB*HH*NQ)        // 4800
#define MKV (BB*LTOT)           // 10752 rows for K/V projections
#define QPAD 384                // padded query rows per (b,h) for 128-tiles
#define SCALE 0.17677669529663687f  // 1/sqrt(32)

// ---------------- scratch (device globals; allocation-free) ----------------
__device__ float g_q[BB*NQ*CC];
__device__ float g_attn[(size_t)BB*HH*NQ*LTOT];   // raw scaled logits
__device__ float g_f2[BB*NQ*L2SZ*HH];
__device__ float g_f3[BB*NQ*L3SZ*HH];
__device__ float g_x[BB*NQ*CC];
__device__ float g_pm[(size_t)NROWS*NT2];
__device__ float g_ps[(size_t)NROWS*NT2];
__device__ float g_rowm[NROWS];
__device__ float g_rowinv[NROWS];
__device__ __nv_bfloat16 g_kimg[(size_t)MKV*512];       // key   input hi|lo split [r][512]
__device__ __nv_bfloat16 g_vimg[(size_t)MKV*512];       // value input hi|lo split
__device__ __nv_bfloat16 g_wk[256*512];                 // Wk^T hi|lo image [n][512]
__device__ __nv_bfloat16 g_wv[256*512];                 // Wv^T hi|lo image
__device__ __nv_bfloat16 g_kh[(size_t)BB*HH*LTOT*64];   // projected K head image [bh][l][hi32|lo32]
__device__ __nv_bfloat16 g_vh[(size_t)BB*HH*LTOT*64];   // projected V head image [bh][l][hi32|lo32]
__device__ __nv_bfloat16 g_qh[(size_t)BB*HH*QPAD*64];   // projected Q head image [bh][row][hi32|lo32]

// ================= mma.sync helpers =================
__device__ __forceinline__ uint32_t smem_u32(const void* p) {
    uint32_t a;
    asm("{ .reg .u64 t; cvta.to.shared.u64 t, %1; cvt.u32.u64 %0, t; }" : "=r"(a) : "l"(p));
    return a;
}
#define LDSM4(r, addr) \
    asm volatile("ldmatrix.sync.aligned.m8n8.x4.shared.b16 {%0,%1,%2,%3}, [%4];" \
        : "=r"((r)[0]), "=r"((r)[1]), "=r"((r)[2]), "=r"((r)[3]) : "r"(addr))
#define LDSM4T(r, addr) \
    asm volatile("ldmatrix.sync.aligned.m8n8.x4.trans.shared.b16 {%0,%1,%2,%3}, [%4];" \
        : "=r"((r)[0]), "=r"((r)[1]), "=r"((r)[2]), "=r"((r)[3]) : "r"(addr))
#define MMA16816(dd, aa, b0, b1) \
    asm volatile("mma.sync.aligned.m16n8k16.row.col.f32.bf16.bf16.f32 " \
        "{%0,%1,%2,%3},{%4,%5,%6,%7},{%8,%9},{%0,%1,%2,%3};" \
        : "+f"((dd)[0]), "+f"((dd)[1]), "+f"((dd)[2]), "+f"((dd)[3]) \
        : "r"((aa)[0]), "r"((aa)[1]), "r"((aa)[2]), "r"((aa)[3]), "r"(b0), "r"(b1))

// ---------------- prep: split fp32 rows into [hi(256)|lo(256)] bf16 image ----
__global__ void prep_split_kernel(const float* __restrict__ A, __nv_bfloat16* __restrict__ img,
                                  int M)
{
    int idx = blockIdx.x * blockDim.x + threadIdx.x;
    if (idx >= M * 64) return;
    int r = idx >> 6, c4 = (idx & 63) * 4;
    float4 v = *(const float4*)(A + (size_t)r * 256 + c4);
    __nv_bfloat16 hi[4], lo[4];
    hi[0] = __float2bfloat16(v.x); lo[0] = __float2bfloat16(v.x - __bfloat162float(hi[0]));
    hi[1] = __float2bfloat16(v.y); lo[1] = __float2bfloat16(v.y - __bfloat162float(hi[1]));
    hi[2] = __float2bfloat16(v.z); lo[2] = __float2bfloat16(v.z - __bfloat162float(hi[2]));
    hi[3] = __float2bfloat16(v.w); lo[3] = __float2bfloat16(v.w - __bfloat162float(hi[3]));
    *(uint2*)(img + (size_t)r * 512 + c4)       = *(uint2*)hi;
    *(uint2*)(img + (size_t)r * 512 + 256 + c4) = *(uint2*)lo;
}

// ---------------- prep: W[k][n] -> Wt image [n][ hi k(256) | lo k(256) ] ----
__global__ void prep_wt_kernel(const float* __restrict__ W, __nv_bfloat16* __restrict__ img)
{
    int n = blockIdx.x;
    int k = threadIdx.x;
    float x = W[(size_t)k * 256 + n];
    __nv_bfloat16 h = __float2bfloat16(x);
    img[(size_t)n * 512 + k]       = h;
    img[(size_t)n * 512 + 256 + k] = __float2bfloat16(x - __bfloat162float(h));
}

// ---------------- prep: q fp32 -> padded head-split image [bh][row<384][64] --
__global__ void prep_q_kernel(const float* __restrict__ Q, __nv_bfloat16* __restrict__ img)
{
    int idx = blockIdx.x * blockDim.x + threadIdx.x;   // 16*384*32 = 196608
    if (idx >= BB*HH*QPAD*32) return;
    int c   = idx & 31;
    int row = (idx >> 5) % QPAD;
    int bh  = idx / (QPAD * 32);
    int b = bh >> 3, h = bh & 7;
    float x = (row < NQ) ? Q[((size_t)b*NQ + row)*CC + h*32 + c] : 0.f;
    __nv_bfloat16 hi = __float2bfloat16(x);
    __nv_bfloat16* dst = img + ((size_t)bh * QPAD + row) * 64;
    dst[c]      = hi;
    dst[32 + c] = __float2bfloat16(x - __bfloat162float(hi));
}

// ---------------- tensor-core projection: C = A @ W via bf16 split ----------
// mode 0: write fp32 rows to Cout.  mode 1: write bf16 head-split image to Hout.
#define PSTR 72
__global__ void __launch_bounds__(256)
proj_mma_kernel(const __nv_bfloat16* __restrict__ Aimg, const __nv_bfloat16* __restrict__ Wimg,
                float* __restrict__ Cout, __nv_bfloat16* __restrict__ Hout, int mode)
{
    extern __shared__ __align__(16) char dsm[];
    __nv_bfloat16* sA  = (__nv_bfloat16*)dsm;
    __nv_bfloat16* sB1 = (__nv_bfloat16*)(dsm + 128*PSTR*2);
    __nv_bfloat16* sB2 = (__nv_bfloat16*)(dsm + 2*128*PSTR*2);
    const int tid = threadIdx.x;
    const int lane = tid & 31, wid = tid >> 5;
    const int wm = (wid & 3) * 32;
    const int wn = (wid >> 2) * 64;
    const int m0 = blockIdx.y * 128;
    const int n0 = blockIdx.x * 128;

    float d[2][8][4];
    #pragma unroll
    for (int i = 0; i < 2; i++)
        #pragma unroll
        for (int j = 0; j < 8; j++)
            #pragma unroll
            for (int q = 0; q < 4; q++) d[i][j][q] = 0.f;

    const uint32_t sa_u = smem_u32(sA), sb1_u = smem_u32(sB1), sb2_u = smem_u32(sB2);

    for (int kc = 0; kc < 512; kc += 64) {
        int kc2 = (kc + 256) & 511;
        for (int i = tid; i < 1024; i += 256) {
            int r = i >> 3, c = i & 7;
            *(uint4*)(sA + r * PSTR + c * 8) =
                *(const uint4*)(Aimg + (size_t)(m0 + r) * 512 + kc + c * 8);
        }
        for (int i = tid; i < 1024; i += 256) {
            int r = i >> 3, c = i & 7;
            const __nv_bfloat16* wrow = Wimg + (size_t)(n0 + r) * 512;
            *(uint4*)(sB1 + r * PSTR + c * 8) = *(const uint4*)(wrow + kc  + c * 8);
            *(uint4*)(sB2 + r * PSTR + c * 8) = *(const uint4*)(wrow + kc2 + c * 8);
        }
        __syncthreads();
        #pragma unroll
        for (int ks = 0; ks < 4; ks++) {
            uint32_t a[2][4];
            #pragma unroll
            for (int am = 0; am < 2; am++) {
                uint32_t addr = sa_u +
                    ((uint32_t)((wm + am*16 + (lane & 15)) * PSTR + ks*16 + (lane >> 4)*8) << 1);
                LDSM4(a[am], addr);
            }
            #pragma unroll
            for (int p = 0; p < 4; p++) {
                uint32_t boff = ((uint32_t)((wn + p*16 + (lane & 7) + ((lane >> 4) << 3)) * PSTR
                                 + ks*16 + ((lane >> 3) & 1) * 8) << 1);
                uint32_t b[4];
                LDSM4(b, sb1_u + boff);
                MMA16816(d[0][2*p],   a[0], b[0], b[1]);
                MMA16816(d[0][2*p+1], a[0], b[2], b[3]);
                MMA16816(d[1][2*p],   a[1], b[0], b[1]);
                MMA16816(d[1][2*p+1], a[1], b[2], b[3]);
                LDSM4(b, sb2_u + boff);
                MMA16816(d[0][2*p],   a[0], b[0], b[1]);
                MMA16816(d[0][2*p+1], a[0], b[2], b[3]);
                MMA16816(d[1][2*p],   a[1], b[0], b[1]);
                MMA16816(d[1][2*p+1], a[1], b[2], b[3]);
            }
        }
        __syncthreads();
    }

    if (mode == 0) {
        #pragma unroll
        for (int am = 0; am < 2; am++) {
            int rbase = m0 + wm + am * 16 + (lane >> 2);
            #pragma unroll
            for (int na = 0; na < 8; na++) {
                int col = n0 + wn + na * 8 + (lane & 3) * 2;
                float* p0 = Cout + (size_t)rbase * 256 + col;
                p0[0] = d[am][na][0]; p0[1] = d[am][na][1];
                float* p1 = Cout + (size_t)(rbase + 8) * 256 + col;
                p1[0] = d[am][na][2]; p1[1] = d[am][na][3];
            }
        }
    } else {
        // head-split bf16 image: [b*HH+h][l][hi c | lo c]
        #pragma unroll
        for (int am = 0; am < 2; am++) {
            int r0 = m0 + wm + am * 16 + (lane >> 2);
            #pragma unroll
            for (int rr = 0; rr < 2; rr++) {
                int r = r0 + rr * 8;
                int b = r / LTOT, l = r - b * LTOT;
                #pragma unroll
                for (int na = 0; na < 8; na++) {
                    int col = n0 + wn + na * 8 + (lane & 3) * 2;
                    int h = col >> 5, c = col & 31;
                    __nv_bfloat16* dst = Hout + ((size_t)(b*HH + h)*LTOT + l)*64;
                    float x0 = d[am][na][rr*2], x1 = d[am][na][rr*2 + 1];
                    __nv_bfloat16 h0 = __float2bfloat16(x0);
                    __nv_bfloat16 h1 = __float2bfloat16(x1);
                    __nv_bfloat16 v2[2];
                    v2[0] = h0; v2[1] = h1;
                    *(uint32_t*)(dst + c) = *(uint32_t*)v2;
                    v2[0] = __float2bfloat16(x0 - __bfloat162float(h0));
                    v2[1] = __float2bfloat16(x1 - __bfloat162float(h1));
                    *(uint32_t*)(dst + 32 + c) = *(uint32_t*)v2;
                }
            }
        }
    }
}

// ---------------- attention logits on tensor cores + softmax partials -------
// grid (42 l-tiles, 3 m-tiles, 16 bh), 256 threads; K'=64 hi|lo with cross terms
__global__ void __launch_bounds__(256)
attn_mma_kernel(const __nv_bfloat16* __restrict__ Qimg, const __nv_bfloat16* __restrict__ Kimg,
                float* __restrict__ attn, float* __restrict__ pm, float* __restrict__ ps)
{
    __shared__ __align__(16) __nv_bfloat16 sA[128*PSTR];
    __shared__ __align__(16) __nv_bfloat16 sB[128*PSTR];
    const int tid = threadIdx.x;
    const int lane = tid & 31, wid = tid >> 5;
    const int wm = (wid & 3) * 32;
    const int wn = (wid >> 2) * 64;
    const int bh = blockIdx.z;
    const int m0 = blockIdx.y * 128;
    const int l0 = blockIdx.x * 128;

    for (int i = tid; i < 1024; i += 256) {
        int r = i >> 3, c = i & 7;
        *(uint4*)(sA + r * PSTR + c * 8) =
            *(const uint4*)(Qimg + ((size_t)bh * QPAD + m0 + r) * 64 + c * 8);
    }
    for (int i = tid; i < 1024; i += 256) {
        int r = i >> 3, c = i & 7;
        *(uint4*)(sB + r * PSTR + c * 8) =
            *(const uint4*)(Kimg + ((size_t)bh * LTOT + l0 + r) * 64 + c * 8);
    }
    __syncthreads();

    const uint32_t sa_u = smem_u32(sA), sb_u = smem_u32(sB);
    float d[2][8][4];
    #pragma unroll
    for (int i = 0; i < 2; i++)
        #pragma unroll
        for (int j = 0; j < 8; j++)
            #pragma unroll
            for (int q = 0; q < 4; q++) d[i][j][q] = 0.f;

    #pragma unroll
    for (int ks = 0; ks < 4; ks++) {
        int ksx = ks ^ 2;   // swapped-half index for cross terms
        uint32_t a[2][4];
        #pragma unroll
        for (int am = 0; am < 2; am++) {
            uint32_t addr = sa_u +
                ((uint32_t)((wm + am*16 + (lane & 15)) * PSTR + ks*16 + (lane >> 4)*8) << 1);
            LDSM4(a[am], addr);
        }
        #pragma unroll
        for (int p = 0; p < 4; p++) {
            uint32_t rowterm = (uint32_t)((wn + p*16 + (lane & 7) + ((lane >> 4) << 3)) * PSTR
                               + ((lane >> 3) & 1) * 8);
            uint32_t b[4];
            // direct: q_half(ks) · k_half(ks)
            LDSM4(b, sb_u + ((rowterm + ks*16) << 1));
            MMA16816(d[0][2*p],   a[0], b[0], b[1]);
            MMA16816(d[0][2*p+1], a[0], b[2], b[3]);
            MMA16816(d[1][2*p],   a[1], b[0], b[1]);
            MMA16816(d[1][2*p+1], a[1], b[2], b[3]);
            // cross: q_half(ks) · k_half(ks^2)
            LDSM4(b, sb_u + ((rowterm + ksx*16) << 1));
            MMA16816(d[0][2*p],   a[0], b[0], b[1]);
            MMA16816(d[0][2*p+1], a[0], b[2], b[3]);
            MMA16816(d[1][2*p],   a[1], b[0], b[1]);
            MMA16816(d[1][2*p+1], a[1], b[2], b[3]);
        }
    }

    // epilogue: scale, store logits, per-row (max, sumexp) over this 64-col span
    int tileIdx = blockIdx.x * 2 + (wn >> 6);
    #pragma unroll
    for (int am = 0; am < 2; am++) {
        int r0 = m0 + wm + am * 16 + (lane >> 2);
        #pragma unroll
        for (int q = 0; q < 4; q++)
            #pragma unroll
            for (int na = 0; na < 8; na++) d[am][na][q] *= SCALE;

        #pragma unroll
        for (int rr = 0; rr < 2; rr++) {
            int row = r0 + rr * 8;
            bool ok = row < NQ;
            float v0max = -1e30f, sum = 0.f;
            #pragma unroll
            for (int na = 0; na < 8; na++) {
                float x0 = d[am][na][rr*2], x1 = d[am][na][rr*2+1];
                v0max = fmaxf(v0max, fmaxf(x0, x1));
            }
            v0max = fmaxf(v0max, __shfl_xor_sync(0xffffffffu, v0max, 1));
            v0max = fmaxf(v0max, __shfl_xor_sync(0xffffffffu, v0max, 2));
            #pragma unroll
            for (int na = 0; na < 8; na++) {
                float x0 = d[am][na][rr*2], x1 = d[am][na][rr*2+1];
                sum += __expf(x0 - v0max) + __expf(x1 - v0max);
                if (ok) {
                    float2 o; o.x = x0; o.y = x1;
                    *(float2*)&attn[((size_t)bh*NQ + row)*LTOT + l0 + wn + na*8 + (lane & 3)*2] = o;
                }
            }
            sum += __shfl_xor_sync(0xffffffffu, sum, 1);
            sum += __shfl_xor_sync(0xffffffffu, sum, 2);
            if (ok && (lane & 3) == 0) {
                size_t pidx = ((size_t)bh*NQ + row)*NT2 + tileIdx;
                pm[pidx] = v0max;
                ps[pidx] = sum;
            }
        }
    }
}

// ---------------- projection GEMM (small M): C[M,256] = A @ W (+bias) ----------
__global__ void proj_gemm_kernel(const float* __restrict__ A, const float* __restrict__ W,
                                 const float* __restrict__ bias, float* __restrict__ Cout,
                                 int M)
{
    __shared__ float As[16][68];
    __shared__ float Bs[16][68];
    int tid = threadIdx.x;
    int bm = blockIdx.y * 64;
    int bn = blockIdx.x * 64;
    int tm = (tid >> 4) * 8;
    int tn = (tid & 15) * 4;
    float acc[8][4];
    #pragma unroll
    for (int i = 0; i < 8; i++)
        #pragma unroll
        for (int j = 0; j < 4; j++) acc[i][j] = 0.f;

    for (int k0 = 0; k0 < 256; k0 += 16) {
        for (int i = tid; i < 64*16; i += 128) {
            int m = i >> 4, kk = i & 15;
            int row = bm + m;
            As[kk][m] = (row < M) ? A[(size_t)row*256 + k0 + kk] : 0.f;
        }
        for (int i = tid; i < 16*64; i += 128) {
            int kk = i >> 6, n = i & 63;
            Bs[kk][n] = W[(k0 + kk)*256 + bn + n];
        }
        __syncthreads();
        #pragma unroll
        for (int kk = 0; kk < 16; kk++) {
            float a[8], bb[4];
            *(float4*)&a[0] = *(const float4*)&As[kk][tm];
            *(float4*)&a[4] = *(const float4*)&As[kk][tm+4];
            *(float4*)&bb[0] = *(const float4*)&Bs[kk][tn];
            #pragma unroll
            for (int i = 0; i < 8; i++)
                #pragma unroll
                for (int j = 0; j < 4; j++)
                    acc[i][j] = fmaf(a[i], bb[j], acc[i][j]);
        }
        __syncthreads();
    }
    #pragma unroll
    for (int i = 0; i < 8; i++) {
        int row = bm + tm + i;
        if (row >= M) continue;
        #pragma unroll
        for (int j = 0; j < 4; j++) {
            float v = acc[i][j];
            if (bias) v += bias[bn + tn + j];
            Cout[(size_t)row*256 + bn + tn + j] = v;
        }
    }
}

// ---------------- combine per-tile partials into per-row (max, 1/sum) -------
__global__ void softstats_kernel(const float* __restrict__ pm, const float* __restrict__ ps,
                                 float* __restrict__ rowm, float* __restrict__ rowinv)
{
    int row = blockIdx.x * 8 + (threadIdx.x >> 5);
    int lane = threadIdx.x & 31;
    size_t base = (size_t)row * NT2;
    float m = -1e30f;
    for (int i = lane; i < NT2; i += 32) m = fmaxf(m, pm[base + i]);
    #pragma unroll
    for (int s = 16; s > 0; s >>= 1)
        m = fmaxf(m, __shfl_xor_sync(0xffffffffu, m, s));
    float ssum = 0.f;
    for (int i = lane; i < NT2; i += 32) ssum += ps[base + i] * __expf(pm[base + i] - m);
    #pragma unroll
    for (int s = 16; s > 0; s >>= 1)
        ssum += __shfl_xor_sync(0xffffffffu, ssum, s);
    if (lane == 0) {
        rowm[row] = m;
        rowinv[row] = 1.f / ssum;
    }
}

// ---------------- f2/f3 small fields: relu(ap @ W + b), channel-last --------
__global__ void f23_kernel(const float* __restrict__ attn,
                           const float* __restrict__ W2, const float* __restrict__ b2,
                           const float* __restrict__ W3, const float* __restrict__ b3,
                           float* __restrict__ f2o, float* __restrict__ f3o)
{
    int bn = blockIdx.y;
    int b = bn / NQ, n = bn % NQ;
    int j = blockIdx.x * blockDim.x + threadIdx.x;
    if (j >= L2SZ + L3SZ) return;

    int lidx = (j < L2SZ) ? (L2OFF + j) : (L3OFF + (j - L2SZ));
    size_t base = ((size_t)(b*HH)*NQ + n)*LTOT + lidx;
    float a[8];
    #pragma unroll
    for (int hh = 0; hh < 8; hh++)
        a[hh] = attn[base + (size_t)hh * NL];

    if (j < L2SZ) {
        float* dst = f2o + ((size_t)bn * L2SZ + j) * 8;
        #pragma unroll
        for (int h = 0; h < 8; h++) {
            float s = b2[h];
            #pragma unroll
            for (int hh = 0; hh < 8; hh++) s = fmaf(a[hh], W2[hh*8 + h], s);
            dst[h] = fmaxf(s, 0.f);
        }
    } else {
        int jj = j - L2SZ;
        float* dst = f3o + ((size_t)bn * L3SZ + jj) * 8;
        #pragma unroll
        for (int h = 0; h < 8; h++) {
            float s = b3[h];
            #pragma unroll
            for (int hh = 0; hh < 8; hh++) s = fmaf(a[hh], W3[hh*8 + h], s);
            dst[h] = fmaxf(s, 0.f);
        }
    }
}

// ---------------- fused mask: f1 + bilinear(f2) + bilinear(f3), dot Wm, relu -
__global__ void mask_kernel(const float* __restrict__ attn,
                            const float* __restrict__ f2f, const float* __restrict__ f3f,
                            const float* __restrict__ W1, const float* __restrict__ b1,
                            const float* __restrict__ Wm, const float* __restrict__ bm,
                            float* __restrict__ outmask)
{
    __shared__ float sW1[64], sb1[8], sWm[24], sbm[1];
    int t = threadIdx.x;
    if (t < 64) sW1[t] = W1[t];
    if (t < 8)  sb1[t] = b1[t];
    if (t < 24) sWm[t] = Wm[t];
    if (t == 0) sbm[0] = bm[0];
    __syncthreads();

    int bn = blockIdx.y;
    int b = bn / NQ, n = bn % NQ;
    int p = blockIdx.x * blockDim.x + t;
    int Y = p >> 6, X = p & 63;

    size_t base = ((size_t)(b*HH)*NQ + n)*LTOT + p;
    float a[8];
    #pragma unroll
    for (int hh = 0; hh < 8; hh++)
        a[hh] = attn[base + (size_t)hh * NL];

    float acc = sbm[0];
    #pragma unroll
    for (int h = 0; h < 8; h++) {
        float s = sb1[h];
        #pragma unroll
        for (int hh = 0; hh < 8; hh++) s = fmaf(a[hh], sW1[hh*8 + h], s);
        acc = fmaf(fmaxf(s, 0.f), sWm[h], acc);
    }

    {   // f2: bilinear from 32x32
        float ry = fminf(fmaxf(0.5f*(float)Y - 0.25f, 0.f), 31.f);
        float rx = fminf(fmaxf(0.5f*(float)X - 0.25f, 0.f), 31.f);
        int y0 = (int)ry, x0 = (int)rx;
        int y1 = min(y0+1, 31), x1 = min(x0+1, 31);
        float wy = ry - (float)y0, wx = rx - (float)x0;
        float w00 = (1.f-wy)*(1.f-wx), w01 = (1.f-wy)*wx, w10 = wy*(1.f-wx), w11 = wy*wx;
        const float* fb = f2f + (size_t)bn * (L2SZ*8);
        const float* t00 = fb + (y0*32 + x0)*8;
        const float* t01 = fb + (y0*32 + x1)*8;
        const float* t10 = fb + (y1*32 + x0)*8;
        const float* t11 = fb + (y1*32 + x1)*8;
        #pragma unroll
        for (int h = 0; h < 8; h++) {
            float v = w00*t00[h] + w01*t01[h] + w10*t10[h] + w11*t11[h];
            acc = fmaf(v, sWm[8 + h], acc);
        }
    }
    {   // f3: bilinear from 16x16
        float ry = fminf(fmaxf(0.25f*(float)Y - 0.375f, 0.f), 15.f);
        float rx = fminf(fmaxf(0.25f*(float)X - 0.375f, 0.f), 15.f);
        int y0 = (int)ry, x0 = (int)rx;
        int y1 = min(y0+1, 15), x1 = min(x0+1, 15);
        float wy = ry - (float)y0, wx = rx - (float)x0;
        float w00 = (1.f-wy)*(1.f-wx), w01 = (1.f-wy)*wx, w10 = wy*(1.f-wx), w11 = wy*wx;
        const float* fb = f3f + (size_t)bn * (L3SZ*8);
        const float* t00 = fb + (y0*16 + x0)*8;
        const float* t01 = fb + (y0*16 + x1)*8;
        const float* t10 = fb + (y1*16 + x0)*8;
        const float* t11 = fb + (y1*16 + x1)*8;
        #pragma unroll
        for (int h = 0; h < 8; h++) {
            float v = w00*t00[h] + w01*t01[h] + w10*t10[h] + w11*t11[h];
            acc = fmaf(v, sWm[16 + h], acc);
        }
    }
    outmask[(size_t)bn * L1SZ + p] = fmaxf(acc, 0.f);
}

// ---------------- zero ----
__global__ void zero_kernel(float* __restrict__ p, int n)
{
    int i = blockIdx.x * blockDim.x + threadIdx.x;
    if (i < n) p[i] = 0.f;
}

// ---------------- AV on tensor cores: probs hi/lo x V hi/lo ------------------
// grid (6 l-splits of 896, 3 m-tiles, 16 bh), 256 threads
#define AVPSTR 264   // probs tile row stride (elems): 128 hi | 128 lo | 8 pad
#define AVVSTR 72    // V tile row stride (elems): 64 + 8 pad
#define AV_SMEM (128*AVPSTR*2 + 128*AVVSTR*2 + 256*4)
__global__ void __launch_bounds__(256)
av_mma_kernel(const float* __restrict__ attn, const __nv_bfloat16* __restrict__ Vimg,
              const float* __restrict__ rowm, const float* __restrict__ rowinv,
              float* __restrict__ X)
{
    extern __shared__ __align__(16) char dsm[];
    __nv_bfloat16* sP = (__nv_bfloat16*)dsm;                        // [128][264]
    __nv_bfloat16* sV = (__nv_bfloat16*)(dsm + 128*AVPSTR*2);       // [128][72]
    float* srm = (float*)(dsm + 128*AVPSTR*2 + 128*AVVSTR*2);
    float* sri = srm + 128;

    const int tid = threadIdx.x;
    const int lane = tid & 31, wid = tid >> 5;
    const int bh = blockIdx.z, b = bh >> 3, h = bh & 7;
    const int m0 = blockIdx.y * 128;
    const int lbase = blockIdx.x * 896;
    const int wm = wid * 16;   // 8 warps x 16 rows

    if (tid < 128) {
        int row = m0 + tid;
        bool ok = row < NQ;
        srm[tid] = ok ? rowm[(size_t)bh*NQ + row] : 0.f;
        sri[tid] = ok ? rowinv[(size_t)bh*NQ + row] : 0.f;
    }
    __syncthreads();

    const uint32_t sp_u = smem_u32(sP), sv_u = smem_u32(sV);

    float d[4][4];   // 4 d8-groups
    #pragma unroll
    for (int g = 0; g < 4; g++)
        #pragma unroll
        for (int q = 0; q < 4; q++) d[g][q] = 0.f;

    for (int kc = 0; kc < 896; kc += 128) {
        int l0 = lbase + kc;
        // V tile [128 l][hi32|lo32]
        for (int i = tid; i < 1024; i += 256) {
            int r = i >> 3, c = i & 7;
            *(uint4*)(sV + r * AVVSTR + c * 8) =
                *(const uint4*)(Vimg + ((size_t)bh * LTOT + l0 + r) * 64 + c * 8);
        }
        // probs tile: read logits, exp, hi/lo split
        for (int i = tid; i < 128*32; i += 256) {
            int r = i >> 5, c4 = (i & 31) * 4;
            int row = m0 + r;
            __nv_bfloat16 hi[4], lo[4];
            if (row < NQ) {
                float4 v = *(const float4*)(attn + ((size_t)bh*NQ + row)*LTOT + l0 + c4);
                float mr = srm[r], ir = sri[r];
                float p0 = __expf(v.x - mr) * ir;
                float p1 = __expf(v.y - mr) * ir;
                float p2 = __expf(v.z - mr) * ir;
                float p3 = __expf(v.w - mr) * ir;
                hi[0] = __float2bfloat16(p0); lo[0] = __float2bfloat16(p0 - __bfloat162float(hi[0]));
                hi[1] = __float2bfloat16(p1); lo[1] = __float2bfloat16(p1 - __bfloat162float(hi[1]));
                hi[2] = __float2bfloat16(p2); lo[2] = __float2bfloat16(p2 - __bfloat162float(hi[2]));
                hi[3] = __float2bfloat16(p3); lo[3] = __float2bfloat16(p3 - __bfloat162float(hi[3]));
            } else {
                hi[0]=hi[1]=hi[2]=hi[3]=__float2bfloat16(0.f);
                lo[0]=lo[1]=lo[2]=lo[3]=__float2bfloat16(0.f);
            }
            *(uint2*)(sP + r * AVPSTR + c4)       = *(uint2*)hi;
            *(uint2*)(sP + r * AVPSTR + 128 + c4) = *(uint2*)lo;
        }
        __syncthreads();

        #pragma unroll
        for (int ks = 0; ks < 8; ks++) {
            uint32_t ah[4], al[4];
            uint32_t aaddr = sp_u +
                ((uint32_t)((wm + (lane & 15)) * AVPSTR + ks*16 + (lane >> 4)*8) << 1);
            LDSM4(ah, aaddr);
            LDSM4(al, aaddr + (128 << 1));
            // B frags via ldmatrix.trans from k-major V tile
            // lane: g = lane>>4 (d8-group within call), kk = ((lane>>3)&1)*8 + (lane&7)
            int g_l = lane >> 4;
            int kk  = ((lane >> 3) & 1) * 8 + (lane & 7);
            uint32_t bhv[2][4], blv[2][4];
            #pragma unroll
            for (int call = 0; call < 2; call++) {
                uint32_t baddr = sv_u +
                    ((uint32_t)((ks*16 + kk) * AVVSTR + call*16 + g_l*8) << 1);
                LDSM4T(bhv[call], baddr);
                LDSM4T(blv[call], baddr + (32 << 1));
            }
            #pragma unroll
            for (int g = 0; g < 4; g++) {
                uint32_t* Bh = &bhv[g >> 1][(g & 1) * 2];
                uint32_t* Bl = &blv[g >> 1][(g & 1) * 2];
                MMA16816(d[g], ah, Bh[0], Bh[1]);   // Ph * Vh
                MMA16816(d[g], ah, Bl[0], Bl[1]);   // Ph * Vl
                MMA16816(d[g], al, Bh[0], Bh[1]);   // Pl * Vh
            }
        }
        __syncthreads();
    }

    // epilogue: atomic accumulate into X
    #pragma unroll
    for (int g = 0; g < 4; g++) {
        int dcol = h*32 + g*8 + (lane & 3)*2;
        int row0 = m0 + wm + (lane >> 2);
        if (row0 < NQ) {
            atomicAdd(&X[((size_t)b*NQ + row0)*CC + dcol    ], d[g][0]);
            atomicAdd(&X[((size_t)b*NQ + row0)*CC + dcol + 1], d[g][1]);
        }
        int row1 = row0 + 8;
        if (row1 < NQ) {
            atomicAdd(&X[((size_t)b*NQ + row1)*CC + dcol    ], d[g][2]);
            atomicAdd(&X[((size_t)b*NQ + row1)*CC + dcol + 1], d[g][3]);
        }
    }
}

// ---------------- launch ----
extern "C" void kernel_launch(void* const* d_in, const int* in_sizes, int n_in,
                              void* d_out, int out_size)
{
    const float* query = (const float*)d_in[0];
    const float* key   = (const float*)d_in[1];
    const float* value = (const float*)d_in[2];
    const float* Wq = (const float*)d_in[5];
    const float* Wk = (const float*)d_in[6];
    const float* Wv = (const float*)d_in[7];
    const float* Wp = (const float*)d_in[8];
    const float* bp = (const float*)d_in[9];
    const float* W1 = (const float*)d_in[10];
    const float* b1 = (const float*)d_in[11];
    const float* W2 = (const float*)d_in[12];
    const float* b2 = (const float*)d_in[13];
    const float* W3 = (const float*)d_in[14];
    const float* b3 = (const float*)d_in[15];
    const float* Wm = (const float*)d_in[16];
    const float* bm = (const float*)d_in[17];

    float* out_x    = (float*)d_out;
    float* out_mask = (float*)d_out + BB*NQ*CC;

    float *gq, *gattn, *gf2, *gf3, *gx, *gpm, *gps, *grm, *gri;
    __nv_bfloat16 *gkimg, *gvimg, *gwk, *gwv, *gkh, *gvh, *gqh;
    cudaGetSymbolAddress((void**)&gq,    g_q);
    cudaGetSymbolAddress((void**)&gattn, g_attn);
    cudaGetSymbolAddress((void**)&gf2,   g_f2);
    cudaGetSymbolAddress((void**)&gf3,   g_f3);
    cudaGetSymbolAddress((void**)&gx,    g_x);
    cudaGetSymbolAddress((void**)&gpm,   g_pm);
    cudaGetSymbolAddress((void**)&gps,   g_ps);
    cudaGetSymbolAddress((void**)&grm,   g_rowm);
    cudaGetSymbolAddress((void**)&gri,   g_rowinv);
    cudaGetSymbolAddress((void**)&gkimg, g_kimg);
    cudaGetSymbolAddress((void**)&gvimg, g_vimg);
    cudaGetSymbolAddress((void**)&gwk,   g_wk);
    cudaGetSymbolAddress((void**)&gwv,   g_wv);
    cudaGetSymbolAddress((void**)&gkh,   g_kh);
    cudaGetSymbolAddress((void**)&gvh,   g_vh);
    cudaGetSymbolAddress((void**)&gqh,   g_qh);

    const int PROJ_SMEM = 3 * 128 * PSTR * 2;
    cudaFuncSetAttribute(proj_mma_kernel, cudaFuncAttributeMaxDynamicSharedMemorySize, PROJ_SMEM);
    cudaFuncSetAttribute(av_mma_kernel, cudaFuncAttributeMaxDynamicSharedMemorySize, AV_SMEM);

    // 1a) split-precision input images
    prep_split_kernel<<<(MKV*64 + 255)/256, 256>>>(key,   gkimg, MKV);
    prep_split_kernel<<<(MKV*64 + 255)/256, 256>>>(value, gvimg, MKV);
    prep_wt_kernel<<<256, 256>>>(Wk, gwk);
    prep_wt_kernel<<<256, 256>>>(Wv, gwv);

    // 1b) K/V projections on tensor cores; both write head-split bf16 images
    proj_mma_kernel<<<dim3(2, 84), 256, PROJ_SMEM>>>(gkimg, gwk, nullptr, gkh, 1);
    proj_mma_kernel<<<dim3(2, 84), 256, PROJ_SMEM>>>(gvimg, gwv, nullptr, gvh, 1);

    // 1c) Q projection (small fp32) + head-split padded image
    proj_gemm_kernel<<<dim3(4, 10), 128>>>(query, Wq, nullptr, gq, BB*NQ);
    prep_q_kernel<<<(BB*HH*QPAD*32 + 255)/256, 256>>>(gq, gqh);

    // 2) attention logits on tensor cores (with cross terms) + softmax partials
    attn_mma_kernel<<<dim3(NT2/2, 3, BB*HH), 256>>>(gqh, gkh, gattn, gpm, gps);

    // 3) per-row softmax stats
    softstats_kernel<<<NROWS/8, 256>>>(gpm, gps, grm, gri);

    // 4) mask path (reads raw logits)
    f23_kernel<<<dim3(5, 600), 256>>>(gattn, W2, b2, W3, b3, gf2, gf3);
    mask_kernel<<<dim3(32, 600), 128>>>(gattn, gf2, gf3, W1, b1, Wm, bm, out_mask);

    // 5) AV on tensor cores (probs hi/lo x V hi/lo), 6-way L split
    zero_kernel<<<(BB*NQ*CC + 255)/256, 256>>>(gx, BB*NQ*CC);
    av_mma_kernel<<<dim3(6, 3, BB*HH), 256, AV_SMEM>>>(gattn, gvh, grm, gri, gx);

    // 6) output projection
    proj_gemm_kernel<<<dim3(4, 10), 128>>>(gx, Wp, bp, out_x, BB*NQ);
}

// round 17
// speedup vs baseline: 2.1046x; 1.0380x over previous
#include <cuda_runtime.h>
#include <cuda_bf16.h>
#include <cstdint>
#include <math.h>

// Problem constants
#define BB 2
#define NQ 300
#define CC 256
#define HH 8
#define DD 32
#define LTOT 5376
#define L1SZ 4096   // 64x64
#define L2OFF 4096
#define L2SZ 1024   // 32x32
#define L3OFF 5120
#define L3SZ 256    // 16x16
#define NL (NQ*LTOT)            // 1,612,800
#define NT2 84                  // 64-col softmax partial tiles per row (5376/64)
#define NROWS (BB*HH*NQ)        // 4800
#define MKV (BB*LTOT)           // 10752 rows for K/V projections
#define QPAD 384                // padded query rows per (b,h) for 128-tiles
#define SCALE 0.17677669529663687f  // 1/sqrt(32)

// ---------------- scratch (device globals; allocation-free) ----------------
__device__ float g_q[BB*NQ*CC];
__device__ float g_attn[(size_t)BB*HH*NQ*LTOT];   // raw scaled logits
__device__ float g_x[BB*NQ*CC];
__device__ float g_pm[(size_t)NROWS*NT2];
__device__ float g_ps[(size_t)NROWS*NT2];
__device__ float g_rowm[NROWS];
__device__ float g_rowinv[NROWS];
__device__ __nv_bfloat16 g_kimg[(size_t)MKV*512];       // key   input hi|lo split [r][512]
__device__ __nv_bfloat16 g_vimg[(size_t)MKV*512];       // value input hi|lo split
__device__ __nv_bfloat16 g_wk[256*512];                 // Wk^T hi|lo image [n][512]
__device__ __nv_bfloat16 g_wv[256*512];                 // Wv^T hi|lo image
__device__ __nv_bfloat16 g_kh[(size_t)BB*HH*LTOT*64];   // projected K head image [bh][l][hi32|lo32]
__device__ __nv_bfloat16 g_vh[(size_t)BB*HH*LTOT*64];   // projected V head image [bh][l][hi32|lo32]
__device__ __nv_bfloat16 g_qh[(size_t)BB*HH*QPAD*64];   // projected Q head image [bh][row][hi32|lo32]

// ================= mma.sync helpers =================
__device__ __forceinline__ uint32_t smem_u32(const void* p) {
    uint32_t a;
    asm("{ .reg .u64 t; cvta.to.shared.u64 t, %1; cvt.u32.u64 %0, t; }" : "=r"(a) : "l"(p));
    return a;
}
#define LDSM4(r, addr) \
    asm volatile("ldmatrix.sync.aligned.m8n8.x4.shared.b16 {%0,%1,%2,%3}, [%4];" \
        : "=r"((r)[0]), "=r"((r)[1]), "=r"((r)[2]), "=r"((r)[3]) : "r"(addr))
#define LDSM4T(r, addr) \
    asm volatile("ldmatrix.sync.aligned.m8n8.x4.trans.shared.b16 {%0,%1,%2,%3}, [%4];" \
        : "=r"((r)[0]), "=r"((r)[1]), "=r"((r)[2]), "=r"((r)[3]) : "r"(addr))
#define MMA16816(dd, aa, b0, b1) \
    asm volatile("mma.sync.aligned.m16n8k16.row.col.f32.bf16.bf16.f32 " \
        "{%0,%1,%2,%3},{%4,%5,%6,%7},{%8,%9},{%0,%1,%2,%3};" \
        : "+f"((dd)[0]), "+f"((dd)[1]), "+f"((dd)[2]), "+f"((dd)[3]) \
        : "r"((aa)[0]), "r"((aa)[1]), "r"((aa)[2]), "r"((aa)[3]), "r"(b0), "r"(b1))

// ---------------- prep: split fp32 rows into [hi(256)|lo(256)] bf16 image ----
__global__ void prep_split_kernel(const float* __restrict__ A, __nv_bfloat16* __restrict__ img,
                                  int M)
{
    int idx = blockIdx.x * blockDim.x + threadIdx.x;
    if (idx >= M * 64) return;
    int r = idx >> 6, c4 = (idx & 63) * 4;
    float4 v = *(const float4*)(A + (size_t)r * 256 + c4);
    __nv_bfloat16 hi[4], lo[4];
    hi[0] = __float2bfloat16(v.x); lo[0] = __float2bfloat16(v.x - __bfloat162float(hi[0]));
    hi[1] = __float2bfloat16(v.y); lo[1] = __float2bfloat16(v.y - __bfloat162float(hi[1]));
    hi[2] = __float2bfloat16(v.z); lo[2] = __float2bfloat16(v.z - __bfloat162float(hi[2]));
    hi[3] = __float2bfloat16(v.w); lo[3] = __float2bfloat16(v.w - __bfloat162float(hi[3]));
    *(uint2*)(img + (size_t)r * 512 + c4)       = *(uint2*)hi;
    *(uint2*)(img + (size_t)r * 512 + 256 + c4) = *(uint2*)lo;
}

// ---------------- prep: W[k][n] -> Wt image [n][ hi k(256) | lo k(256) ] ----
__global__ void prep_wt_kernel(const float* __restrict__ W, __nv_bfloat16* __restrict__ img)
{
    int n = blockIdx.x;
    int k = threadIdx.x;
    float x = W[(size_t)k * 256 + n];
    __nv_bfloat16 h = __float2bfloat16(x);
    img[(size_t)n * 512 + k]       = h;
    img[(size_t)n * 512 + 256 + k] = __float2bfloat16(x - __bfloat162float(h));
}

// ---------------- prep: q fp32 -> padded head-split image [bh][row<384][64] --
__global__ void prep_q_kernel(const float* __restrict__ Q, __nv_bfloat16* __restrict__ img)
{
    int idx = blockIdx.x * blockDim.x + threadIdx.x;   // 16*384*32 = 196608
    if (idx >= BB*HH*QPAD*32) return;
    int c   = idx & 31;
    int row = (idx >> 5) % QPAD;
    int bh  = idx / (QPAD * 32);
    int b = bh >> 3, h = bh & 7;
    float x = (row < NQ) ? Q[((size_t)b*NQ + row)*CC + h*32 + c] : 0.f;
    __nv_bfloat16 hi = __float2bfloat16(x);
    __nv_bfloat16* dst = img + ((size_t)bh * QPAD + row) * 64;
    dst[c]      = hi;
    dst[32 + c] = __float2bfloat16(x - __bfloat162float(hi));
}

// ---------------- tensor-core projection: C = A @ W via bf16 split ----------
// lo*lo terms dropped (kc>=256 aligned pass skipped): ~4e-6 relative, 25% fewer MMAs.
// mode 0: write fp32 rows to Cout.  mode 1: write bf16 head-split image to Hout.
#define PSTR 72
__global__ void __launch_bounds__(256)
proj_mma_kernel(const __nv_bfloat16* __restrict__ Aimg, const __nv_bfloat16* __restrict__ Wimg,
                float* __restrict__ Cout, __nv_bfloat16* __restrict__ Hout, int mode)
{
    extern __shared__ __align__(16) char dsm[];
    __nv_bfloat16* sA  = (__nv_bfloat16*)dsm;
    __nv_bfloat16* sB1 = (__nv_bfloat16*)(dsm + 128*PSTR*2);
    __nv_bfloat16* sB2 = (__nv_bfloat16*)(dsm + 2*128*PSTR*2);
    const int tid = threadIdx.x;
    const int lane = tid & 31, wid = tid >> 5;
    const int wm = (wid & 3) * 32;
    const int wn = (wid >> 2) * 64;
    const int m0 = blockIdx.y * 128;
    const int n0 = blockIdx.x * 128;

    float d[2][8][4];
    #pragma unroll
    for (int i = 0; i < 2; i++)
        #pragma unroll
        for (int j = 0; j < 8; j++)
            #pragma unroll
            for (int q = 0; q < 4; q++) d[i][j][q] = 0.f;

    const uint32_t sa_u = smem_u32(sA), sb1_u = smem_u32(sB1), sb2_u = smem_u32(sB2);

    for (int kc = 0; kc < 512; kc += 64) {
        const bool doB1 = (kc < 256);   // aligned pass only for hi*hi (skip lo*lo)
        int kc2 = (kc + 256) & 511;
        for (int i = tid; i < 1024; i += 256) {
            int r = i >> 3, c = i & 7;
            *(uint4*)(sA + r * PSTR + c * 8) =
                *(const uint4*)(Aimg + (size_t)(m0 + r) * 512 + kc + c * 8);
        }
        for (int i = tid; i < 1024; i += 256) {
            int r = i >> 3, c = i & 7;
            const __nv_bfloat16* wrow = Wimg + (size_t)(n0 + r) * 512;
            if (doB1)
                *(uint4*)(sB1 + r * PSTR + c * 8) = *(const uint4*)(wrow + kc  + c * 8);
            *(uint4*)(sB2 + r * PSTR + c * 8) = *(const uint4*)(wrow + kc2 + c * 8);
        }
        __syncthreads();
        #pragma unroll
        for (int ks = 0; ks < 4; ks++) {
            uint32_t a[2][4];
            #pragma unroll
            for (int am = 0; am < 2; am++) {
                uint32_t addr = sa_u +
                    ((uint32_t)((wm + am*16 + (lane & 15)) * PSTR + ks*16 + (lane >> 4)*8) << 1);
                LDSM4(a[am], addr);
            }
            #pragma unroll
            for (int p = 0; p < 4; p++) {
                uint32_t boff = ((uint32_t)((wn + p*16 + (lane & 7) + ((lane >> 4) << 3)) * PSTR
                                 + ks*16 + ((lane >> 3) & 1) * 8) << 1);
                uint32_t b[4];
                if (doB1) {
                    LDSM4(b, sb1_u + boff);
                    MMA16816(d[0][2*p],   a[0], b[0], b[1]);
                    MMA16816(d[0][2*p+1], a[0], b[2], b[3]);
                    MMA16816(d[1][2*p],   a[1], b[0], b[1]);
                    MMA16816(d[1][2*p+1], a[1], b[2], b[3]);
                }
                LDSM4(b, sb2_u + boff);
                MMA16816(d[0][2*p],   a[0], b[0], b[1]);
                MMA16816(d[0][2*p+1], a[0], b[2], b[3]);
                MMA16816(d[1][2*p],   a[1], b[0], b[1]);
                MMA16816(d[1][2*p+1], a[1], b[2], b[3]);
            }
        }
        __syncthreads();
    }

    if (mode == 0) {
        #pragma unroll
        for (int am = 0; am < 2; am++) {
            int rbase = m0 + wm + am * 16 + (lane >> 2);
            #pragma unroll
            for (int na = 0; na < 8; na++) {
                int col = n0 + wn + na * 8 + (lane & 3) * 2;
                float* p0 = Cout + (size_t)rbase * 256 + col;
                p0[0] = d[am][na][0]; p0[1] = d[am][na][1];
                float* p1 = Cout + (size_t)(rbase + 8) * 256 + col;
                p1[0] = d[am][na][2]; p1[1] = d[am][na][3];
            }
        }
    } else {
        // head-split bf16 image: [b*HH+h][l][hi c | lo c]
        #pragma unroll
        for (int am = 0; am < 2; am++) {
            int r0 = m0 + wm + am * 16 + (lane >> 2);
            #pragma unroll
            for (int rr = 0; rr < 2; rr++) {
                int r = r0 + rr * 8;
                int b = r / LTOT, l = r - b * LTOT;
                #pragma unroll
                for (int na = 0; na < 8; na++) {
                    int col = n0 + wn + na * 8 + (lane & 3) * 2;
                    int h = col >> 5, c = col & 31;
                    __nv_bfloat16* dst = Hout + ((size_t)(b*HH + h)*LTOT + l)*64;
                    float x0 = d[am][na][rr*2], x1 = d[am][na][rr*2 + 1];
                    __nv_bfloat16 h0 = __float2bfloat16(x0);
                    __nv_bfloat16 h1 = __float2bfloat16(x1);
                    __nv_bfloat16 v2[2];
                    v2[0] = h0; v2[1] = h1;
                    *(uint32_t*)(dst + c) = *(uint32_t*)v2;
                    v2[0] = __float2bfloat16(x0 - __bfloat162float(h0));
                    v2[1] = __float2bfloat16(x1 - __bfloat162float(h1));
                    *(uint32_t*)(dst + 32 + c) = *(uint32_t*)v2;
                }
            }
        }
    }
}

// ---------------- attention logits on tensor cores + softmax partials -------
// grid (42 l-tiles, 3 m-tiles, 16 bh), 256 threads; K'=64 hi|lo; lo*lo dropped
__global__ void __launch_bounds__(256)
attn_mma_kernel(const __nv_bfloat16* __restrict__ Qimg, const __nv_bfloat16* __restrict__ Kimg,
                float* __restrict__ attn, float* __restrict__ pm, float* __restrict__ ps)
{
    __shared__ __align__(16) __nv_bfloat16 sA[128*PSTR];
    __shared__ __align__(16) __nv_bfloat16 sB[128*PSTR];
    const int tid = threadIdx.x;
    const int lane = tid & 31, wid = tid >> 5;
    const int wm = (wid & 3) * 32;
    const int wn = (wid >> 2) * 64;
    const int bh = blockIdx.z;
    const int m0 = blockIdx.y * 128;
    const int l0 = blockIdx.x * 128;

    for (int i = tid; i < 1024; i += 256) {
        int r = i >> 3, c = i & 7;
        *(uint4*)(sA + r * PSTR + c * 8) =
            *(const uint4*)(Qimg + ((size_t)bh * QPAD + m0 + r) * 64 + c * 8);
    }
    for (int i = tid; i < 1024; i += 256) {
        int r = i >> 3, c = i & 7;
        *(uint4*)(sB + r * PSTR + c * 8) =
            *(const uint4*)(Kimg + ((size_t)bh * LTOT + l0 + r) * 64 + c * 8);
    }
    __syncthreads();

    const uint32_t sa_u = smem_u32(sA), sb_u = smem_u32(sB);
    float d[2][8][4];
    #pragma unroll
    for (int i = 0; i < 2; i++)
        #pragma unroll
        for (int j = 0; j < 8; j++)
            #pragma unroll
            for (int q = 0; q < 4; q++) d[i][j][q] = 0.f;

    #pragma unroll
    for (int ks = 0; ks < 4; ks++) {
        int ksx = ks ^ 2;   // swapped-half index for cross terms
        uint32_t a[2][4];
        #pragma unroll
        for (int am = 0; am < 2; am++) {
            uint32_t addr = sa_u +
                ((uint32_t)((wm + am*16 + (lane & 15)) * PSTR + ks*16 + (lane >> 4)*8) << 1);
            LDSM4(a[am], addr);
        }
        #pragma unroll
        for (int p = 0; p < 4; p++) {
            uint32_t rowterm = (uint32_t)((wn + p*16 + (lane & 7) + ((lane >> 4) << 3)) * PSTR
                               + ((lane >> 3) & 1) * 8);
            uint32_t b[4];
            if (ks < 2) {
                // direct: q_hi(ks) · k_hi(ks)   (lo*lo at ks 2,3 dropped: ~4e-6)
                LDSM4(b, sb_u + ((rowterm + ks*16) << 1));
                MMA16816(d[0][2*p],   a[0], b[0], b[1]);
                MMA16816(d[0][2*p+1], a[0], b[2], b[3]);
                MMA16816(d[1][2*p],   a[1], b[0], b[1]);
                MMA16816(d[1][2*p+1], a[1], b[2], b[3]);
            }
            // cross: q_half(ks) · k_half(ks^2)
            LDSM4(b, sb_u + ((rowterm + ksx*16) << 1));
            MMA16816(d[0][2*p],   a[0], b[0], b[1]);
            MMA16816(d[0][2*p+1], a[0], b[2], b[3]);
            MMA16816(d[1][2*p],   a[1], b[0], b[1]);
            MMA16816(d[1][2*p+1], a[1], b[2], b[3]);
        }
    }

    // epilogue: scale, store logits, per-row (max, sumexp) over this 64-col span
    int tileIdx = blockIdx.x * 2 + (wn >> 6);
    #pragma unroll
    for (int am = 0; am < 2; am++) {
        int r0 = m0 + wm + am * 16 + (lane >> 2);
        #pragma unroll
        for (int q = 0; q < 4; q++)
            #pragma unroll
            for (int na = 0; na < 8; na++) d[am][na][q] *= SCALE;

        #pragma unroll
        for (int rr = 0; rr < 2; rr++) {
            int row = r0 + rr * 8;
            bool ok = row < NQ;
            float v0max = -1e30f, sum = 0.f;
            #pragma unroll
            for (int na = 0; na < 8; na++) {
                float x0 = d[am][na][rr*2], x1 = d[am][na][rr*2+1];
                v0max = fmaxf(v0max, fmaxf(x0, x1));
            }
            v0max = fmaxf(v0max, __shfl_xor_sync(0xffffffffu, v0max, 1));
            v0max = fmaxf(v0max, __shfl_xor_sync(0xffffffffu, v0max, 2));
            #pragma unroll
            for (int na = 0; na < 8; na++) {
                float x0 = d[am][na][rr*2], x1 = d[am][na][rr*2+1];
                sum += __expf(x0 - v0max) + __expf(x1 - v0max);
                if (ok) {
                    float2 o; o.x = x0; o.y = x1;
                    *(float2*)&attn[((size_t)bh*NQ + row)*LTOT + l0 + wn + na*8 + (lane & 3)*2] = o;
                }
            }
            sum += __shfl_xor_sync(0xffffffffu, sum, 1);
            sum += __shfl_xor_sync(0xffffffffu, sum, 2);
            if (ok && (lane & 3) == 0) {
                size_t pidx = ((size_t)bh*NQ + row)*NT2 + tileIdx;
                pm[pidx] = v0max;
                ps[pidx] = sum;
            }
        }
    }
}

// ---------------- projection GEMM (small M): C[M,256] = A @ W (+bias) ----------
__global__ void proj_gemm_kernel(const float* __restrict__ A, const float* __restrict__ W,
                                 const float* __restrict__ bias, float* __restrict__ Cout,
                                 int M)
{
    __shared__ float As[16][68];
    __shared__ float Bs[16][68];
    int tid = threadIdx.x;
    int bm = blockIdx.y * 64;
    int bn = blockIdx.x * 64;
    int tm = (tid >> 4) * 8;
    int tn = (tid & 15) * 4;
    float acc[8][4];
    #pragma unroll
    for (int i = 0; i < 8; i++)
        #pragma unroll
        for (int j = 0; j < 4; j++) acc[i][j] = 0.f;

    for (int k0 = 0; k0 < 256; k0 += 16) {
        for (int i = tid; i < 64*16; i += 128) {
            int m = i >> 4, kk = i & 15;
            int row = bm + m;
            As[kk][m] = (row < M) ? A[(size_t)row*256 + k0 + kk] : 0.f;
        }
        for (int i = tid; i < 16*64; i += 128) {
            int kk = i >> 6, n = i & 63;
            Bs[kk][n] = W[(k0 + kk)*256 + bn + n];
        }
        __syncthreads();
        #pragma unroll
        for (int kk = 0; kk < 16; kk++) {
            float a[8], bb[4];
            *(float4*)&a[0] = *(const float4*)&As[kk][tm];
            *(float4*)&a[4] = *(const float4*)&As[kk][tm+4];
            *(float4*)&bb[0] = *(const float4*)&Bs[kk][tn];
            #pragma unroll
            for (int i = 0; i < 8; i++)
                #pragma unroll
                for (int j = 0; j < 4; j++)
                    acc[i][j] = fmaf(a[i], bb[j], acc[i][j]);
        }
        __syncthreads();
    }
    #pragma unroll
    for (int i = 0; i < 8; i++) {
        int row = bm + tm + i;
        if (row >= M) continue;
        #pragma unroll
        for (int j = 0; j < 4; j++) {
            float v = acc[i][j];
            if (bias) v += bias[bn + tn + j];
            Cout[(size_t)row*256 + bn + tn + j] = v;
        }
    }
}

// ---------------- combine per-tile partials into per-row (max, 1/sum) -------
__global__ void softstats_kernel(const float* __restrict__ pm, const float* __restrict__ ps,
                                 float* __restrict__ rowm, float* __restrict__ rowinv)
{
    int row = blockIdx.x * 8 + (threadIdx.x >> 5);
    int lane = threadIdx.x & 31;
    size_t base = (size_t)row * NT2;
    float m = -1e30f;
    for (int i = lane; i < NT2; i += 32) m = fmaxf(m, pm[base + i]);
    #pragma unroll
    for (int s = 16; s > 0; s >>= 1)
        m = fmaxf(m, __shfl_xor_sync(0xffffffffu, m, s));
    float ssum = 0.f;
    for (int i = lane; i < NT2; i += 32) ssum += ps[base + i] * __expf(pm[base + i] - m);
    #pragma unroll
    for (int s = 16; s > 0; s >>= 1)
        ssum += __shfl_xor_sync(0xffffffffu, ssum, s);
    if (lane == 0) {
        rowm[row] = m;
        rowinv[row] = 1.f / ssum;
    }
}

// ---------------- fused f23 + mask: one CTA per (b,n) ------------------------
// phase 1: f2/f3 fields into smem (stride 9, conflict-free bilinear gathers)
// phase 2: f1 + bilinear(f2s) + bilinear(f3s), dot Wm, relu -> outmask
__global__ void __launch_bounds__(256)
fmask_kernel(const float* __restrict__ attn,
             const float* __restrict__ W1, const float* __restrict__ b1,
             const float* __restrict__ W2, const float* __restrict__ b2,
             const float* __restrict__ W3, const float* __restrict__ b3,
             const float* __restrict__ Wm, const float* __restrict__ bm,
             float* __restrict__ outmask)
{
    __shared__ float f2s[L2SZ * 9];   // 36864 B
    __shared__ float f3s[L3SZ * 9];   // 9216 B
    __shared__ float sW1[64], sW2[64], sW3[64], sb1[8], sb2[8], sb3[8], sWm[24], sbm[1];
    int t = threadIdx.x;
    if (t < 64) { sW1[t] = W1[t]; sW2[t] = W2[t]; sW3[t] = W3[t]; }
    if (t < 8)  { sb1[t] = b1[t]; sb2[t] = b2[t]; sb3[t] = b3[t]; }
    if (t < 24) sWm[t] = Wm[t];
    if (t == 0) sbm[0] = bm[0];
    __syncthreads();

    int bn = blockIdx.x;
    int b = bn / NQ, n = bn % NQ;
    size_t rowbase = ((size_t)(b*HH)*NQ + n)*LTOT;

    // phase 1: f2/f3
    for (int j = t; j < L2SZ + L3SZ; j += 256) {
        int lidx = (j < L2SZ) ? (L2OFF + j) : (L3OFF + (j - L2SZ));
        size_t base = rowbase + lidx;
        float a[8];
        #pragma unroll
        for (int hh = 0; hh < 8; hh++)
            a[hh] = attn[base + (size_t)hh * NL];
        float* dst;
        const float* W; const float* bias;
        if (j < L2SZ) { dst = f2s + j * 9;          W = sW2; bias = sb2; }
        else          { dst = f3s + (j - L2SZ) * 9; W = sW3; bias = sb3; }
        #pragma unroll
        for (int h = 0; h < 8; h++) {
            float s = bias[h];
            #pragma unroll
            for (int hh = 0; hh < 8; hh++) s = fmaf(a[hh], W[hh*8 + h], s);
            dst[h] = fmaxf(s, 0.f);
        }
    }
    __syncthreads();

    // phase 2: mask over 64x64
    for (int p = t; p < L1SZ; p += 256) {
        int Y = p >> 6, X = p & 63;
        size_t base = rowbase + p;
        float a[8];
        #pragma unroll
        for (int hh = 0; hh < 8; hh++)
            a[hh] = attn[base + (size_t)hh * NL];

        float acc = sbm[0];
        #pragma unroll
        for (int h = 0; h < 8; h++) {
            float s = sb1[h];
            #pragma unroll
            for (int hh = 0; hh < 8; hh++) s = fmaf(a[hh], sW1[hh*8 + h], s);
            acc = fmaf(fmaxf(s, 0.f), sWm[h], acc);
        }

        {   // f2: bilinear from 32x32 (smem)
            float ry = fminf(fmaxf(0.5f*(float)Y - 0.25f, 0.f), 31.f);
            float rx = fminf(fmaxf(0.5f*(float)X - 0.25f, 0.f), 31.f);
            int y0 = (int)ry, x0 = (int)rx;
            int y1 = min(y0+1, 31), x1 = min(x0+1, 31);
            float wy = ry - (float)y0, wx = rx - (float)x0;
            float w00 = (1.f-wy)*(1.f-wx), w01 = (1.f-wy)*wx, w10 = wy*(1.f-wx), w11 = wy*wx;
            const float* t00 = f2s + (y0*32 + x0)*9;
            const float* t01 = f2s + (y0*32 + x1)*9;
            const float* t10 = f2s + (y1*32 + x0)*9;
            const float* t11 = f2s + (y1*32 + x1)*9;
            #pragma unroll
            for (int h = 0; h < 8; h++) {
                float v = w00*t00[h] + w01*t01[h] + w10*t10[h] + w11*t11[h];
                acc = fmaf(v, sWm[8 + h], acc);
            }
        }
        {   // f3: bilinear from 16x16 (smem)
            float ry = fminf(fmaxf(0.25f*(float)Y - 0.375f, 0.f), 15.f);
            float rx = fminf(fmaxf(0.25f*(float)X - 0.375f, 0.f), 15.f);
            int y0 = (int)ry, x0 = (int)rx;
            int y1 = min(y0+1, 15), x1 = min(x0+1, 15);
            float wy = ry - (float)y0, wx = rx - (float)x0;
            float w00 = (1.f-wy)*(1.f-wx), w01 = (1.f-wy)*wx, w10 = wy*(1.f-wx), w11 = wy*wx;
            const float* t00 = f3s + (y0*16 + x0)*9;
            const float* t01 = f3s + (y0*16 + x1)*9;
            const float* t10 = f3s + (y1*16 + x0)*9;
            const float* t11 = f3s + (y1*16 + x1)*9;
            #pragma unroll
            for (int h = 0; h < 8; h++) {
                float v = w00*t00[h] + w01*t01[h] + w10*t10[h] + w11*t11[h];
                acc = fmaf(v, sWm[16 + h], acc);
            }
        }
        outmask[(size_t)bn * L1SZ + p] = fmaxf(acc, 0.f);
    }
}

// ---------------- zero ----
__global__ void zero_kernel(float* __restrict__ p, int n)
{
    int i = blockIdx.x * blockDim.x + threadIdx.x;
    if (i < n) p[i] = 0.f;
}

// ---------------- AV on tensor cores: probs hi/lo x V hi/lo ------------------
// grid (6 l-splits of 896, 3 m-tiles, 16 bh), 256 threads
#define AVPSTR 264   // probs tile row stride (elems): 128 hi | 128 lo | 8 pad
#define AVVSTR 72    // V tile row stride (elems): 64 + 8 pad
#define AV_SMEM (128*AVPSTR*2 + 128*AVVSTR*2 + 256*4)
__global__ void __launch_bounds__(256)
av_mma_kernel(const float* __restrict__ attn, const __nv_bfloat16* __restrict__ Vimg,
              const float* __restrict__ rowm, const float* __restrict__ rowinv,
              float* __restrict__ X)
{
    extern __shared__ __align__(16) char dsm[];
    __nv_bfloat16* sP = (__nv_bfloat16*)dsm;                        // [128][264]
    __nv_bfloat16* sV = (__nv_bfloat16*)(dsm + 128*AVPSTR*2);       // [128][72]
    float* srm = (float*)(dsm + 128*AVPSTR*2 + 128*AVVSTR*2);
    float* sri = srm + 128;

    const int tid = threadIdx.x;
    const int lane = tid & 31, wid = tid >> 5;
    const int bh = blockIdx.z, b = bh >> 3, h = bh & 7;
    const int m0 = blockIdx.y * 128;
    const int lbase = blockIdx.x * 896;
    const int wm = wid * 16;   // 8 warps x 16 rows

    if (tid < 128) {
        int row = m0 + tid;
        bool ok = row < NQ;
        srm[tid] = ok ? rowm[(size_t)bh*NQ + row] : 0.f;
        sri[tid] = ok ? rowinv[(size_t)bh*NQ + row] : 0.f;
    }
    __syncthreads();

    const uint32_t sp_u = smem_u32(sP), sv_u = smem_u32(sV);

    float d[4][4];   // 4 d8-groups
    #pragma unroll
    for (int g = 0; g < 4; g++)
        #pragma unroll
        for (int q = 0; q < 4; q++) d[g][q] = 0.f;

    for (int kc = 0; kc < 896; kc += 128) {
        int l0 = lbase + kc;
        // V tile [128 l][hi32|lo32]
        for (int i = tid; i < 1024; i += 256) {
            int r = i >> 3, c = i & 7;
            *(uint4*)(sV + r * AVVSTR + c * 8) =
                *(const uint4*)(Vimg + ((size_t)bh * LTOT + l0 + r) * 64 + c * 8);
        }
        // probs tile: read logits, exp, hi/lo split
        for (int i = tid; i < 128*32; i += 256) {
            int r = i >> 5, c4 = (i & 31) * 4;
            int row = m0 + r;
            __nv_bfloat16 hi[4], lo[4];
            if (row < NQ) {
                float4 v = *(const float4*)(attn + ((size_t)bh*NQ + row)*LTOT + l0 + c4);
                float mr = srm[r], ir = sri[r];
                float p0 = __expf(v.x - mr) * ir;
                float p1 = __expf(v.y - mr) * ir;
                float p2 = __expf(v.z - mr) * ir;
                float p3 = __expf(v.w - mr) * ir;
                hi[0] = __float2bfloat16(p0); lo[0] = __float2bfloat16(p0 - __bfloat162float(hi[0]));
                hi[1] = __float2bfloat16(p1); lo[1] = __float2bfloat16(p1 - __bfloat162float(hi[1]));
                hi[2] = __float2bfloat16(p2); lo[2] = __float2bfloat16(p2 - __bfloat162float(hi[2]));
                hi[3] = __float2bfloat16(p3); lo[3] = __float2bfloat16(p3 - __bfloat162float(hi[3]));
            } else {
                hi[0]=hi[1]=hi[2]=hi[3]=__float2bfloat16(0.f);
                lo[0]=lo[1]=lo[2]=lo[3]=__float2bfloat16(0.f);
            }
            *(uint2*)(sP + r * AVPSTR + c4)       = *(uint2*)hi;
            *(uint2*)(sP + r * AVPSTR + 128 + c4) = *(uint2*)lo;
        }
        __syncthreads();

        #pragma unroll
        for (int ks = 0; ks < 8; ks++) {
            uint32_t ah[4], al[4];
            uint32_t aaddr = sp_u +
                ((uint32_t)((wm + (lane & 15)) * AVPSTR + ks*16 + (lane >> 4)*8) << 1);
            LDSM4(ah, aaddr);
            LDSM4(al, aaddr + (128 << 1));
            // B frags via ldmatrix.trans from k-major V tile
            int g_l = lane >> 4;
            int kk  = ((lane >> 3) & 1) * 8 + (lane & 7);
            uint32_t bhv[2][4], blv[2][4];
            #pragma unroll
            for (int call = 0; call < 2; call++) {
                uint32_t baddr = sv_u +
                    ((uint32_t)((ks*16 + kk) * AVVSTR + call*16 + g_l*8) << 1);
                LDSM4T(bhv[call], baddr);
                LDSM4T(blv[call], baddr + (32 << 1));
            }
            #pragma unroll
            for (int g = 0; g < 4; g++) {
                uint32_t* Bh = &bhv[g >> 1][(g & 1) * 2];
                uint32_t* Bl = &blv[g >> 1][(g & 1) * 2];
                MMA16816(d[g], ah, Bh[0], Bh[1]);   // Ph * Vh
                MMA16816(d[g], ah, Bl[0], Bl[1]);   // Ph * Vl
                MMA16816(d[g], al, Bh[0], Bh[1]);   // Pl * Vh
            }
        }
        __syncthreads();
    }

    // epilogue: atomic accumulate into X
    #pragma unroll
    for (int g = 0; g < 4; g++) {
        int dcol = h*32 + g*8 + (lane & 3)*2;
        int row0 = m0 + wm + (lane >> 2);
        if (row0 < NQ) {
            atomicAdd(&X[((size_t)b*NQ + row0)*CC + dcol    ], d[g][0]);
            atomicAdd(&X[((size_t)b*NQ + row0)*CC + dcol + 1], d[g][1]);
        }
        int row1 = row0 + 8;
        if (row1 < NQ) {
            atomicAdd(&X[((size_t)b*NQ + row1)*CC + dcol    ], d[g][2]);
            atomicAdd(&X[((size_t)b*NQ + row1)*CC + dcol + 1], d[g][3]);
        }
    }
}

// ---------------- launch ----
extern "C" void kernel_launch(void* const* d_in, const int* in_sizes, int n_in,
                              void* d_out, int out_size)
{
    const float* query = (const float*)d_in[0];
    const float* key   = (const float*)d_in[1];
    const float* value = (const float*)d_in[2];
    const float* Wq = (const float*)d_in[5];
    const float* Wk = (const float*)d_in[6];
    const float* Wv = (const float*)d_in[7];
    const float* Wp = (const float*)d_in[8];
    const float* bp = (const float*)d_in[9];
    const float* W1 = (const float*)d_in[10];
    const float* b1 = (const float*)d_in[11];
    const float* W2 = (const float*)d_in[12];
    const float* b2 = (const float*)d_in[13];
    const float* W3 = (const float*)d_in[14];
    const float* b3 = (const float*)d_in[15];
    const float* Wm = (const float*)d_in[16];
    const float* bm = (const float*)d_in[17];

    float* out_x    = (float*)d_out;
    float* out_mask = (float*)d_out + BB*NQ*CC;

    float *gq, *gattn, *gx, *gpm, *gps, *grm, *gri;
    __nv_bfloat16 *gkimg, *gvimg, *gwk, *gwv, *gkh, *gvh, *gqh;
    cudaGetSymbolAddress((void**)&gq,    g_q);
    cudaGetSymbolAddress((void**)&gattn, g_attn);
    cudaGetSymbolAddress((void**)&gx,    g_x);
    cudaGetSymbolAddress((void**)&gpm,   g_pm);
    cudaGetSymbolAddress((void**)&gps,   g_ps);
    cudaGetSymbolAddress((void**)&grm,   g_rowm);
    cudaGetSymbolAddress((void**)&gri,   g_rowinv);
    cudaGetSymbolAddress((void**)&gkimg, g_kimg);
    cudaGetSymbolAddress((void**)&gvimg, g_vimg);
    cudaGetSymbolAddress((void**)&gwk,   g_wk);
    cudaGetSymbolAddress((void**)&gwv,   g_wv);
    cudaGetSymbolAddress((void**)&gkh,   g_kh);
    cudaGetSymbolAddress((void**)&gvh,   g_vh);
    cudaGetSymbolAddress((void**)&gqh,   g_qh);

    const int PROJ_SMEM = 3 * 128 * PSTR * 2;
    cudaFuncSetAttribute(proj_mma_kernel, cudaFuncAttributeMaxDynamicSharedMemorySize, PROJ_SMEM);
    cudaFuncSetAttribute(av_mma_kernel, cudaFuncAttributeMaxDynamicSharedMemorySize, AV_SMEM);

    // 1a) split-precision input images
    prep_split_kernel<<<(MKV*64 + 255)/256, 256>>>(key,   gkimg, MKV);
    prep_split_kernel<<<(MKV*64 + 255)/256, 256>>>(value, gvimg, MKV);
    prep_wt_kernel<<<256, 256>>>(Wk, gwk);
    prep_wt_kernel<<<256, 256>>>(Wv, gwv);

    // 1b) K/V projections on tensor cores; both write head-split bf16 images
    proj_mma_kernel<<<dim3(2, 84), 256, PROJ_SMEM>>>(gkimg, gwk, nullptr, gkh, 1);
    proj_mma_kernel<<<dim3(2, 84), 256, PROJ_SMEM>>>(gvimg, gwv, nullptr, gvh, 1);

    // 1c) Q projection (small fp32) + head-split padded image
    proj_gemm_kernel<<<dim3(4, 10), 128>>>(query, Wq, nullptr, gq, BB*NQ);
    prep_q_kernel<<<(BB*HH*QPAD*32 + 255)/256, 256>>>(gq, gqh);

    // 2) attention logits on tensor cores + softmax partials
    attn_mma_kernel<<<dim3(NT2/2, 3, BB*HH), 256>>>(gqh, gkh, gattn, gpm, gps);

    // 3) per-row softmax stats
    softstats_kernel<<<NROWS/8, 256>>>(gpm, gps, grm, gri);

    // 4) fused f23 + mask (reads raw logits, smem intermediate)
    fmask_kernel<<<BB*NQ, 256>>>(gattn, W1, b1, W2, b2, W3, b3, Wm, bm, out_mask);

    // 5) AV on tensor cores (probs hi/lo x V hi/lo), 6-way L split
    zero_kernel<<<(BB*NQ*CC + 255)/256, 256>>>(gx, BB*NQ*CC);
    av_mma_kernel<<<dim3(6, 3, BB*HH), 256, AV_SMEM>>>(gattn, gvh, grm, gri, gx);

    // 6) output projection
    proj_gemm_kernel<<<dim3(4, 10), 128>>>(gx, Wp, bp, out_x, BB*NQ);
}